// round 1
// baseline (speedup 1.0000x reference)
#include <cuda_runtime.h>
#include <math.h>

#define NN   262144
#define NG   2048
#define DX   256
#define DG   128
#define DIN  384
#define HID  256
#define TM   64
#define BK   16
#define PAD  68
#define BN_EPS 1e-3f

// Per-graph normalizer scratch (no device allocs allowed)
__device__ float g_norm[NG];

__global__ void zero_norm_kernel() {
    g_norm[blockIdx.x * 256 + threadIdx.x] = 0.0f;
}

// smem layout (floats):
//   sA : [DIN][PAD]  k-major input tile (row padded to 68 for alignment/conflicts)
//        -- reused after GEMM1 as sH : [HID][PAD]
//   sB : [BK][HID]   weight k-tile
//   sIdx: [TM] ints  batch indices for this row tile
#define SMEM_FLOATS (DIN * PAD + BK * HID)
#define SMEM_BYTES  (SMEM_FLOATS * 4 + TM * 4)

__global__ __launch_bounds__(256, 1) void att_kernel(
    const float* __restrict__ x, const int* __restrict__ bidx,
    const float* __restrict__ gf,
    const float* __restrict__ W0, const float* __restrict__ b0,
    const float* __restrict__ W1, const float* __restrict__ b1,
    const float* __restrict__ W2, const float* __restrict__ b2,
    const float* __restrict__ gamma0, const float* __restrict__ beta0,
    const float* __restrict__ mean0, const float* __restrict__ var0,
    const float* __restrict__ gamma1, const float* __restrict__ beta1,
    const float* __restrict__ mean1, const float* __restrict__ var1,
    float* __restrict__ out)
{
    extern __shared__ float smem[];
    float* sA = smem;                        // [DIN][PAD]
    float* sB = smem + DIN * PAD;            // [BK][HID]
    int*   sIdx = (int*)(smem + SMEM_FLOATS);

    const int tid = threadIdx.x;
    const int tx = tid & 15;        // N-dim (cols tx + 16*j)
    const int ty = tid >> 4;        // M-dim (rows ty*4 + i)
    const int row0 = blockIdx.x * TM;

    if (tid < TM) sIdx[tid] = bidx[row0 + tid];
    __syncthreads();

    // --- Load A tile: [x | gf[batch]] 64 x 384, stored k-major sA[k][row] ---
    // 64 rows * 96 float4 each = 6144 float4; 24 per thread; coalesced in gmem.
    for (int it = tid; it < TM * (DIN / 4); it += 256) {
        int r  = it / (DIN / 4);
        int kq = it % (DIN / 4);
        float4 v;
        if (kq < DX / 4)
            v = *(const float4*)(x + (size_t)(row0 + r) * DX + kq * 4);
        else
            v = *(const float4*)(gf + (size_t)sIdx[r] * DG + (kq * 4 - DX));
        sA[(kq * 4 + 0) * PAD + r] = v.x;
        sA[(kq * 4 + 1) * PAD + r] = v.y;
        sA[(kq * 4 + 2) * PAD + r] = v.z;
        sA[(kq * 4 + 3) * PAD + r] = v.w;
    }
    __syncthreads();

    float c[4][16];

    // ================= GEMM1: (64 x 384) @ W0 (384 x 256) =================
    #pragma unroll
    for (int i = 0; i < 4; i++)
        #pragma unroll
        for (int j = 0; j < 16; j++) c[i][j] = 0.0f;

    for (int kt = 0; kt < DIN; kt += BK) {
        // load W0 k-tile into sB (16 x 256), coalesced float4
        for (int it = tid; it < BK * HID / 4; it += 256)
            ((float4*)sB)[it] = ((const float4*)(W0 + (size_t)kt * HID))[it];
        __syncthreads();
        #pragma unroll
        for (int kk = 0; kk < BK; kk++) {
            float4 a4 = *(const float4*)&sA[(kt + kk) * PAD + ty * 4];
            float a[4] = {a4.x, a4.y, a4.z, a4.w};
            float b[16];
            #pragma unroll
            for (int j = 0; j < 16; j++) b[j] = sB[kk * HID + tx + 16 * j];
            #pragma unroll
            for (int i = 0; i < 4; i++)
                #pragma unroll
                for (int j = 0; j < 16; j++)
                    c[i][j] = fmaf(a[i], b[j], c[i][j]);
        }
        __syncthreads();   // before sB is overwritten next iter
    }

    // BN0 (folded affine) + ReLU, store h1 k-major into sH (aliases sA)
    float* sH = sA;   // [HID][PAD]
    // (all reads of sA done; the __syncthreads at loop end covers the hazard)
    #pragma unroll
    for (int j = 0; j < 16; j++) {
        int col = tx + 16 * j;
        float s  = gamma0[col] * rsqrtf(var0[col] + BN_EPS);
        float sh = fmaf(b0[col] - mean0[col], s, beta0[col]);
        #pragma unroll
        for (int i = 0; i < 4; i++) {
            float v = fmaxf(fmaf(c[i][j], s, sh), 0.0f);
            sH[col * PAD + ty * 4 + i] = v;
        }
    }
    __syncthreads();

    // ================= GEMM2: (64 x 256) @ W1 (256 x 256) =================
    #pragma unroll
    for (int i = 0; i < 4; i++)
        #pragma unroll
        for (int j = 0; j < 16; j++) c[i][j] = 0.0f;

    for (int kt = 0; kt < HID; kt += BK) {
        for (int it = tid; it < BK * HID / 4; it += 256)
            ((float4*)sB)[it] = ((const float4*)(W1 + (size_t)kt * HID))[it];
        __syncthreads();
        #pragma unroll
        for (int kk = 0; kk < BK; kk++) {
            float4 a4 = *(const float4*)&sH[(kt + kk) * PAD + ty * 4];
            float a[4] = {a4.x, a4.y, a4.z, a4.w};
            float b[16];
            #pragma unroll
            for (int j = 0; j < 16; j++) b[j] = sB[kk * HID + tx + 16 * j];
            #pragma unroll
            for (int i = 0; i < 4; i++)
                #pragma unroll
                for (int j = 0; j < 16; j++)
                    c[i][j] = fmaf(a[i], b[j], c[i][j]);
        }
        __syncthreads();
    }

    // BN1 + ReLU + dot with W2 -> partial logits per thread
    float pl[4] = {0.f, 0.f, 0.f, 0.f};
    #pragma unroll
    for (int j = 0; j < 16; j++) {
        int col = tx + 16 * j;
        float s  = gamma1[col] * rsqrtf(var1[col] + BN_EPS);
        float sh = fmaf(b1[col] - mean1[col], s, beta1[col]);
        float w2 = W2[col];
        #pragma unroll
        for (int i = 0; i < 4; i++) {
            float v = fmaxf(fmaf(c[i][j], s, sh), 0.0f);
            pl[i] = fmaf(v, w2, pl[i]);
        }
    }
    // reduce across tx (16 lanes within half-warp)
    #pragma unroll
    for (int off = 8; off > 0; off >>= 1)
        #pragma unroll
        for (int i = 0; i < 4; i++)
            pl[i] += __shfl_xor_sync(0xffffffffu, pl[i], off, 16);

    if (tx == 0) {
        float bb2 = b2[0];
        #pragma unroll
        for (int i = 0; i < 4; i++) {
            int r = ty * 4 + i;
            float a = expf(pl[i] + bb2);
            out[row0 + r] = a;
            atomicAdd(&g_norm[sIdx[r]], a);
        }
    }
}

__global__ void norm_kernel(const int* __restrict__ bidx, float* __restrict__ out) {
    int i = blockIdx.x * 256 + threadIdx.x;
    out[i] = out[i] / g_norm[bidx[i]];
}

extern "C" void kernel_launch(void* const* d_in, const int* in_sizes, int n_in,
                              void* d_out, int out_size) {
    const float* x      = (const float*)d_in[0];
    const int*   bidx   = (const int*)  d_in[1];
    const float* gf     = (const float*)d_in[2];
    const float* W0     = (const float*)d_in[3];
    const float* b0     = (const float*)d_in[4];
    const float* W1     = (const float*)d_in[5];
    const float* b1     = (const float*)d_in[6];
    const float* W2     = (const float*)d_in[7];
    const float* b2     = (const float*)d_in[8];
    const float* gamma0 = (const float*)d_in[9];
    const float* beta0  = (const float*)d_in[10];
    const float* mean0  = (const float*)d_in[11];
    const float* var0   = (const float*)d_in[12];
    const float* gamma1 = (const float*)d_in[13];
    const float* beta1  = (const float*)d_in[14];
    const float* mean1  = (const float*)d_in[15];
    const float* var1   = (const float*)d_in[16];
    float* out = (float*)d_out;

    cudaFuncSetAttribute(att_kernel, cudaFuncAttributeMaxDynamicSharedMemorySize, SMEM_BYTES);

    zero_norm_kernel<<<NG / 256, 256>>>();
    att_kernel<<<NN / TM, 256, SMEM_BYTES>>>(
        x, bidx, gf, W0, b0, W1, b1, W2, b2,
        gamma0, beta0, mean0, var0, gamma1, beta1, mean1, var1, out);
    norm_kernel<<<NN / 256, 256>>>(bidx, out);
}

// round 3
// speedup vs baseline: 3.5216x; 3.5216x over previous
#include <cuda_runtime.h>
#include <cuda_bf16.h>
#include <math.h>
#include <stdint.h>

#define NN   262144
#define NG   2048
#define DX   256
#define DG   128
#define DIN  384
#define HID  256
#define BN_EPS 1e-3f
#define MTILE 128
#define NCTA (NN / MTILE)
#define NTHR 512

// ---- smem byte offsets ----
#define B_HI   0        // 32KB  [256 n][64 k] bf16, 128B rows, swz
#define B_LO   32768
#define A_HI   65536    // 16KB  [128 m][64 k] bf16 (GEMM1 input chunk)
#define A_LO   81920
#define H1_HI  65536    // 64KB  [128 m][256 k] bf16, 512B rows (overlays A after GEMM1)
#define H1_LO  131072
#define SIDX   196608   // 512B
#define PART   197120   // 2KB: float[4][128]
#define P_S0   199168
#define P_SH0  200192
#define P_S1   201216
#define P_SH1  202240
#define P_W2   203264
#define SMEM_TOTAL 204288

__device__ float g_norm[NG];
// pre-split, pre-transposed, pre-swizzled weight images:
// [chunk][n=256][k=64] bf16 with 128B-row XOR swizzle
__device__ __align__(16) uint16_t gW0hi[6 * 16384];
__device__ __align__(16) uint16_t gW0lo[6 * 16384];
__device__ __align__(16) uint16_t gW1hi[4 * 16384];
__device__ __align__(16) uint16_t gW1lo[4 * 16384];

__device__ __forceinline__ uint32_t swz(uint32_t off) {   // 128B-row swizzle
    return off ^ ((off >> 3) & 0x70);
}
__device__ __forceinline__ void bsplit(float f, uint16_t& h, uint16_t& l) {
    __nv_bfloat16 hb = __float2bfloat16(f);
    __nv_bfloat16 lb = __float2bfloat16(f - __bfloat162float(hb));
    h = __bfloat16_as_ushort(hb);
    l = __bfloat16_as_ushort(lb);
}
__device__ __forceinline__ void mma16816(float* c, const uint32_t* a,
                                         uint32_t b0, uint32_t b1) {
    asm volatile(
        "mma.sync.aligned.m16n8k16.row.col.f32.bf16.bf16.f32 "
        "{%0,%1,%2,%3}, {%4,%5,%6,%7}, {%8,%9}, {%0,%1,%2,%3};"
        : "+f"(c[0]), "+f"(c[1]), "+f"(c[2]), "+f"(c[3])
        : "r"(a[0]), "r"(a[1]), "r"(a[2]), "r"(a[3]), "r"(b0), "r"(b1));
}

// ======================= small kernels =======================
__global__ void zero_norm_kernel() {
    g_norm[blockIdx.x * 256 + threadIdx.x] = 0.0f;
}

// W:[K,256] row-major -> per-64k-chunk images [256][64] with swizzle
__global__ void prep_w_kernel(const float* __restrict__ W,
                              uint16_t* __restrict__ hiA,
                              uint16_t* __restrict__ loA) {
    int idx = blockIdx.x * 256 + threadIdx.x;
    int k = idx >> 8, n = idx & 255;
    float v = W[(size_t)k * 256 + n];
    uint16_t h, l;
    bsplit(v, h, l);
    uint32_t off = (uint32_t)(k >> 6) * 32768u + swz((uint32_t)(n * 128 + (k & 63) * 2));
    hiA[off >> 1] = h;
    loA[off >> 1] = l;
}

__global__ void norm_kernel(const int* __restrict__ bidx, float* __restrict__ out) {
    int i = blockIdx.x * 256 + threadIdx.x;
    out[i] = out[i] / g_norm[bidx[i]];
}

// ======================= main fused kernel =======================
__global__ __launch_bounds__(NTHR, 1) void att_kernel(
    const float* __restrict__ x, const int* __restrict__ bidx,
    const float* __restrict__ gf,
    const float* __restrict__ b0,
    const float* __restrict__ W2, const float* __restrict__ b2,
    const float* __restrict__ gamma0, const float* __restrict__ beta0,
    const float* __restrict__ mean0, const float* __restrict__ var0,
    const float* __restrict__ b1,
    const float* __restrict__ gamma1, const float* __restrict__ beta1,
    const float* __restrict__ mean1, const float* __restrict__ var1,
    float* __restrict__ out)
{
    extern __shared__ char smc[];
    const int tid = threadIdx.x;
    const int wid = tid >> 5;
    const int lane = tid & 31;
    const int row0 = blockIdx.x * MTILE;
    const int mw = wid >> 2;          // 0..3  (M groups of 32)
    const int nw = wid & 3;           // 0..3  (N groups of 64)
    const int qr = lane >> 2;         // 0..7
    const int qc = (lane & 3) * 4;    // byte offset for k-pairs

    int* sidx = (int*)(smc + SIDX);
    if (tid < MTILE) sidx[tid] = bidx[row0 + tid];
    // fold BN params
    if (tid < 256) {
        int cc = tid;
        float s0v = gamma0[cc] * rsqrtf(var0[cc] + BN_EPS);
        ((float*)(smc + P_S0))[cc]  = s0v;
        ((float*)(smc + P_SH0))[cc] = fmaf(b0[cc] - mean0[cc], s0v, beta0[cc]);
        float s1v = gamma1[cc] * rsqrtf(var1[cc] + BN_EPS);
        ((float*)(smc + P_S1))[cc]  = s1v;
        ((float*)(smc + P_SH1))[cc] = fmaf(b1[cc] - mean1[cc], s1v, beta1[cc]);
        ((float*)(smc + P_W2))[cc]  = W2[cc];
    }

    float C[2][8][4];
    #pragma unroll
    for (int i = 0; i < 2; i++)
        #pragma unroll
        for (int j = 0; j < 8; j++)
            #pragma unroll
            for (int p = 0; p < 4; p++) C[i][j][p] = 0.0f;

    // =================== GEMM1: [128 x 384] @ W0 ===================
    for (int c = 0; c < 6; c++) {
        __syncthreads();
        // A chunk convert: 128 rows x 64 k  (1024 8-float tasks)
        #pragma unroll
        for (int t = 0; t < 2; t++) {
            int u = tid + t * NTHR;
            int r = u >> 3, q = u & 7;
            const float* s = (c < 4)
                ? (x + (size_t)(row0 + r) * DX + (c << 6) + (q << 3))
                : (gf + (size_t)sidx[r] * DG + ((c - 4) << 6) + (q << 3));
            float4 fa = *(const float4*)s;
            float4 fb = *((const float4*)s + 1);
            uint16_t h[8], l[8];
            bsplit(fa.x, h[0], l[0]); bsplit(fa.y, h[1], l[1]);
            bsplit(fa.z, h[2], l[2]); bsplit(fa.w, h[3], l[3]);
            bsplit(fb.x, h[4], l[4]); bsplit(fb.y, h[5], l[5]);
            bsplit(fb.z, h[6], l[6]); bsplit(fb.w, h[7], l[7]);
            uint32_t off = (uint32_t)(r * 128) + (((uint32_t)(q * 16)) ^ ((r & 7) << 4));
            *(uint4*)(smc + A_HI + off) = make_uint4(
                (uint32_t)h[0] | ((uint32_t)h[1] << 16), (uint32_t)h[2] | ((uint32_t)h[3] << 16),
                (uint32_t)h[4] | ((uint32_t)h[5] << 16), (uint32_t)h[6] | ((uint32_t)h[7] << 16));
            *(uint4*)(smc + A_LO + off) = make_uint4(
                (uint32_t)l[0] | ((uint32_t)l[1] << 16), (uint32_t)l[2] | ((uint32_t)l[3] << 16),
                (uint32_t)l[4] | ((uint32_t)l[5] << 16), (uint32_t)l[6] | ((uint32_t)l[7] << 16));
        }
        // B chunk: flat 32KB hi + 32KB lo
        {
            const uint4* shi = (const uint4*)((const char*)gW0hi + c * 32768);
            const uint4* slo = (const uint4*)((const char*)gW0lo + c * 32768);
            uint4* dhi = (uint4*)(smc + B_HI);
            uint4* dlo = (uint4*)(smc + B_LO);
            #pragma unroll
            for (int i = tid; i < 2048; i += NTHR) { dhi[i] = shi[i]; dlo[i] = slo[i]; }
        }
        __syncthreads();

        #pragma unroll
        for (int ks = 0; ks < 4; ks++) {
            uint32_t ah[2][4], al[2][4];
            #pragma unroll
            for (int i = 0; i < 2; i++) {
                int r = mw * 32 + i * 16 + qr;
                uint32_t xr = (uint32_t)((r & 7) << 4);
                uint32_t base = (uint32_t)(r * 128);
                uint32_t o0 = ((uint32_t)(ks * 32 + qc)) ^ xr;
                uint32_t o2 = ((uint32_t)(ks * 32 + qc + 16)) ^ xr;
                ah[i][0] = *(const uint32_t*)(smc + A_HI + base + o0);
                ah[i][1] = *(const uint32_t*)(smc + A_HI + base + 1024 + o0);
                ah[i][2] = *(const uint32_t*)(smc + A_HI + base + o2);
                ah[i][3] = *(const uint32_t*)(smc + A_HI + base + 1024 + o2);
                al[i][0] = *(const uint32_t*)(smc + A_LO + base + o0);
                al[i][1] = *(const uint32_t*)(smc + A_LO + base + 1024 + o0);
                al[i][2] = *(const uint32_t*)(smc + A_LO + base + o2);
                al[i][3] = *(const uint32_t*)(smc + A_LO + base + 1024 + o2);
            }
            #pragma unroll
            for (int j = 0; j < 8; j++) {
                int n = nw * 64 + j * 8 + qr;
                uint32_t xr = (uint32_t)((n & 7) << 4);
                uint32_t base = (uint32_t)(n * 128);
                uint32_t o0 = ((uint32_t)(ks * 32 + qc)) ^ xr;
                uint32_t o1 = ((uint32_t)(ks * 32 + qc + 16)) ^ xr;
                uint32_t bh0 = *(const uint32_t*)(smc + B_HI + base + o0);
                uint32_t bh1 = *(const uint32_t*)(smc + B_HI + base + o1);
                uint32_t bl0 = *(const uint32_t*)(smc + B_LO + base + o0);
                uint32_t bl1 = *(const uint32_t*)(smc + B_LO + base + o1);
                #pragma unroll
                for (int i = 0; i < 2; i++) {
                    mma16816(C[i][j], ah[i], bh0, bh1);
                    mma16816(C[i][j], ah[i], bl0, bl1);
                    mma16816(C[i][j], al[i], bh0, bh1);
                }
            }
        }
    }
    __syncthreads();   // all GEMM1 smem reads done; A region can be overwritten

    // ====== Epilogue 1: BN0+ReLU, bf16 split, write h1 [128][256] 512B rows ======
    {
        const float* sS0  = (const float*)(smc + P_S0);
        const float* sSH0 = (const float*)(smc + P_SH0);
        #pragma unroll
        for (int i = 0; i < 2; i++) {
            int r = mw * 32 + i * 16 + qr;
            uint32_t xr0 = (uint32_t)((r & 7) << 4);
            uint32_t rb0 = (uint32_t)(r * 512);
            uint32_t rb1 = (uint32_t)((r + 8) * 512);
            #pragma unroll
            for (int j = 0; j < 8; j++) {
                int col = nw * 64 + j * 8 + (lane & 3) * 2;
                float s0a = sS0[col], s0b = sS0[col + 1];
                float h0a = sSH0[col], h0b = sSH0[col + 1];
                float v00 = fmaxf(fmaf(C[i][j][0], s0a, h0a), 0.f);
                float v01 = fmaxf(fmaf(C[i][j][1], s0b, h0b), 0.f);
                float v10 = fmaxf(fmaf(C[i][j][2], s0a, h0a), 0.f);
                float v11 = fmaxf(fmaf(C[i][j][3], s0b, h0b), 0.f);
                uint16_t h00, l00, h01, l01, h10, l10, h11, l11;
                bsplit(v00, h00, l00); bsplit(v01, h01, l01);
                bsplit(v10, h10, l10); bsplit(v11, h11, l11);
                uint32_t ko = ((uint32_t)(col * 2)) ^ xr0;
                *(uint32_t*)(smc + H1_HI + rb0 + ko) = (uint32_t)h00 | ((uint32_t)h01 << 16);
                *(uint32_t*)(smc + H1_LO + rb0 + ko) = (uint32_t)l00 | ((uint32_t)l01 << 16);
                *(uint32_t*)(smc + H1_HI + rb1 + ko) = (uint32_t)h10 | ((uint32_t)h11 << 16);
                *(uint32_t*)(smc + H1_LO + rb1 + ko) = (uint32_t)l10 | ((uint32_t)l11 << 16);
            }
        }
    }

    #pragma unroll
    for (int i = 0; i < 2; i++)
        #pragma unroll
        for (int j = 0; j < 8; j++)
            #pragma unroll
            for (int p = 0; p < 4; p++) C[i][j][p] = 0.0f;

    // =================== GEMM2: h1 [128 x 256] @ W1 ===================
    for (int c = 0; c < 4; c++) {
        __syncthreads();
        {
            const uint4* shi = (const uint4*)((const char*)gW1hi + c * 32768);
            const uint4* slo = (const uint4*)((const char*)gW1lo + c * 32768);
            uint4* dhi = (uint4*)(smc + B_HI);
            uint4* dlo = (uint4*)(smc + B_LO);
            #pragma unroll
            for (int i = tid; i < 2048; i += NTHR) { dhi[i] = shi[i]; dlo[i] = slo[i]; }
        }
        __syncthreads();

        #pragma unroll
        for (int ks = 0; ks < 4; ks++) {
            uint32_t ah[2][4], al[2][4];
            #pragma unroll
            for (int i = 0; i < 2; i++) {
                int r = mw * 32 + i * 16 + qr;
                uint32_t xr = (uint32_t)((r & 7) << 4);
                uint32_t base = (uint32_t)(r * 512);
                uint32_t o0 = ((uint32_t)(c * 128 + ks * 32 + qc)) ^ xr;
                uint32_t o2 = ((uint32_t)(c * 128 + ks * 32 + qc + 16)) ^ xr;
                ah[i][0] = *(const uint32_t*)(smc + H1_HI + base + o0);
                ah[i][1] = *(const uint32_t*)(smc + H1_HI + base + 4096 + o0);
                ah[i][2] = *(const uint32_t*)(smc + H1_HI + base + o2);
                ah[i][3] = *(const uint32_t*)(smc + H1_HI + base + 4096 + o2);
                al[i][0] = *(const uint32_t*)(smc + H1_LO + base + o0);
                al[i][1] = *(const uint32_t*)(smc + H1_LO + base + 4096 + o0);
                al[i][2] = *(const uint32_t*)(smc + H1_LO + base + o2);
                al[i][3] = *(const uint32_t*)(smc + H1_LO + base + 4096 + o2);
            }
            #pragma unroll
            for (int j = 0; j < 8; j++) {
                int n = nw * 64 + j * 8 + qr;
                uint32_t xr = (uint32_t)((n & 7) << 4);
                uint32_t base = (uint32_t)(n * 128);
                uint32_t o0 = ((uint32_t)(ks * 32 + qc)) ^ xr;
                uint32_t o1 = ((uint32_t)(ks * 32 + qc + 16)) ^ xr;
                uint32_t bh0 = *(const uint32_t*)(smc + B_HI + base + o0);
                uint32_t bh1 = *(const uint32_t*)(smc + B_HI + base + o1);
                uint32_t bl0 = *(const uint32_t*)(smc + B_LO + base + o0);
                uint32_t bl1 = *(const uint32_t*)(smc + B_LO + base + o1);
                #pragma unroll
                for (int i = 0; i < 2; i++) {
                    mma16816(C[i][j], ah[i], bh0, bh1);
                    mma16816(C[i][j], ah[i], bl0, bl1);
                    mma16816(C[i][j], al[i], bh0, bh1);
                }
            }
        }
    }

    // ====== Epilogue 2: BN1+ReLU, dot W2, reduce, exp, segment atomics ======
    {
        const float* sS1  = (const float*)(smc + P_S1);
        const float* sSH1 = (const float*)(smc + P_SH1);
        const float* sW2  = (const float*)(smc + P_W2);
        float pl[2][2] = {{0.f, 0.f}, {0.f, 0.f}};
        #pragma unroll
        for (int i = 0; i < 2; i++) {
            #pragma unroll
            for (int j = 0; j < 8; j++) {
                int col = nw * 64 + j * 8 + (lane & 3) * 2;
                float s1a = sS1[col], s1b = sS1[col + 1];
                float h1a = sSH1[col], h1b = sSH1[col + 1];
                float w2a = sW2[col], w2b = sW2[col + 1];
                pl[i][0] = fmaf(fmaxf(fmaf(C[i][j][0], s1a, h1a), 0.f), w2a, pl[i][0]);
                pl[i][0] = fmaf(fmaxf(fmaf(C[i][j][1], s1b, h1b), 0.f), w2b, pl[i][0]);
                pl[i][1] = fmaf(fmaxf(fmaf(C[i][j][2], s1a, h1a), 0.f), w2a, pl[i][1]);
                pl[i][1] = fmaf(fmaxf(fmaf(C[i][j][3], s1b, h1b), 0.f), w2b, pl[i][1]);
            }
        }
        // reduce over lane&3 (quad lanes share the row)
        #pragma unroll
        for (int off = 1; off <= 2; off <<= 1)
            #pragma unroll
            for (int i = 0; i < 2; i++) {
                pl[i][0] += __shfl_xor_sync(0xffffffffu, pl[i][0], off);
                pl[i][1] += __shfl_xor_sync(0xffffffffu, pl[i][1], off);
            }
        float* part = (float*)(smc + PART);
        if ((lane & 3) == 0) {
            #pragma unroll
            for (int i = 0; i < 2; i++) {
                int r = mw * 32 + i * 16 + qr;
                part[nw * 128 + r]     = pl[i][0];
                part[nw * 128 + r + 8] = pl[i][1];
            }
        }
        __syncthreads();
        if (tid < MTILE) {
            float logit = part[tid] + part[128 + tid] + part[256 + tid] +
                          part[384 + tid] + b2[0];
            float av = expf(logit);
            out[row0 + tid] = av;
            atomicAdd(&g_norm[sidx[tid]], av);
        }
    }
}

// ======================= launch =======================
extern "C" void kernel_launch(void* const* d_in, const int* in_sizes, int n_in,
                              void* d_out, int out_size) {
    const float* x      = (const float*)d_in[0];
    const int*   bidx   = (const int*)  d_in[1];
    const float* gf     = (const float*)d_in[2];
    const float* W0     = (const float*)d_in[3];
    const float* b0     = (const float*)d_in[4];
    const float* W1     = (const float*)d_in[5];
    const float* b1     = (const float*)d_in[6];
    const float* W2     = (const float*)d_in[7];
    const float* b2     = (const float*)d_in[8];
    const float* gamma0 = (const float*)d_in[9];
    const float* beta0  = (const float*)d_in[10];
    const float* mean0  = (const float*)d_in[11];
    const float* var0   = (const float*)d_in[12];
    const float* gamma1 = (const float*)d_in[13];
    const float* beta1  = (const float*)d_in[14];
    const float* mean1  = (const float*)d_in[15];
    const float* var1   = (const float*)d_in[16];
    float* out = (float*)d_out;

    static uint16_t *pW0hi = nullptr, *pW0lo, *pW1hi, *pW1lo;
    if (!pW0hi) {
        cudaGetSymbolAddress((void**)&pW0hi, gW0hi);
        cudaGetSymbolAddress((void**)&pW0lo, gW0lo);
        cudaGetSymbolAddress((void**)&pW1hi, gW1hi);
        cudaGetSymbolAddress((void**)&pW1lo, gW1lo);
        cudaFuncSetAttribute(att_kernel, cudaFuncAttributeMaxDynamicSharedMemorySize,
                             SMEM_TOTAL);
    }

    prep_w_kernel<<<DIN, 256>>>(W0, pW0hi, pW0lo);
    prep_w_kernel<<<HID, 256>>>(W1, pW1hi, pW1lo);
    zero_norm_kernel<<<NG / 256, 256>>>();
    att_kernel<<<NCTA, NTHR, SMEM_TOTAL>>>(
        x, bidx, gf, b0, W2, b2,
        gamma0, beta0, mean0, var0,
        b1, gamma1, beta1, mean1, var1, out);
    norm_kernel<<<NN / 256, 256>>>(bidx, out);
}

// round 4
// speedup vs baseline: 3.5568x; 1.0100x over previous
#include <cuda_runtime.h>
#include <cuda_bf16.h>
#include <math.h>
#include <stdint.h>

#define NN   262144
#define NG   2048
#define DX   256
#define DG   128
#define DIN  384
#define HID  256
#define BN_EPS 1e-3f
#define MTILE 128
#define NCTA (NN / MTILE)
#define NTHR 512

// ---- smem byte map ----
#define BSTG   0        // B stages: stage s at s*32768 (hi 16K, lo at +16384); 64KB
#define A_HI   65536    // 16KB  A image hi (Kc=64, 128B rows)
#define A_LO   81920    // 16KB  A image lo
#define H1_HI  98304    // 64KB  h1 hi (512B rows); ALSO A-raw fp32 staging during GEMM1
#define H1_LO  163840   // 64KB  h1 lo
#define SIDX   229376   // 512B
#define PART   229888   // 2KB
#define SMEM_TOTAL 231936
// BN params live in the dead A region after GEMM1
#define P_S0   65536
#define P_SH0  66560
#define P_S1   67584
#define P_SH1  68608
#define P_W2   69632

__device__ float g_norm[NG];
// pre-split, pre-transposed, pre-swizzled weight images:
// per 32-k chunk: [n=256][k=32] bf16, 64B rows, XOR (n&7)<<3
__device__ __align__(16) uint16_t gW0hi[12 * 8192];
__device__ __align__(16) uint16_t gW0lo[12 * 8192];
__device__ __align__(16) uint16_t gW1hi[8 * 8192];
__device__ __align__(16) uint16_t gW1lo[8 * 8192];

// ======================= helpers =======================
__device__ __forceinline__ uint32_t smem_u32(const void* p) {
    uint32_t a;
    asm("{ .reg .u64 t; cvta.to.shared.u64 t, %1; cvt.u32.u64 %0, t; }"
        : "=r"(a) : "l"(p));
    return a;
}
__device__ __forceinline__ void cp16(uint32_t dst, const void* src) {
    asm volatile("cp.async.cg.shared.global [%0], [%1], 16;"
                 :: "r"(dst), "l"(__cvta_generic_to_global(src)) : "memory");
}
#define CP_COMMIT() asm volatile("cp.async.commit_group;" ::: "memory")
#define CP_WAIT1()  asm volatile("cp.async.wait_group 1;" ::: "memory")
#define CP_WAITALL() asm volatile("cp.async.wait_all;" ::: "memory")

__device__ __forceinline__ void bsplit(float f, uint16_t& h, uint16_t& l) {
    __nv_bfloat16 hb = __float2bfloat16(f);
    __nv_bfloat16 lb = __float2bfloat16(f - __bfloat162float(hb));
    h = __bfloat16_as_ushort(hb);
    l = __bfloat16_as_ushort(lb);
}
__device__ __forceinline__ void mma16816(float* c, const uint32_t* a,
                                         uint32_t b0, uint32_t b1) {
    asm volatile(
        "mma.sync.aligned.m16n8k16.row.col.f32.bf16.bf16.f32 "
        "{%0,%1,%2,%3}, {%4,%5,%6,%7}, {%8,%9}, {%0,%1,%2,%3};"
        : "+f"(c[0]), "+f"(c[1]), "+f"(c[2]), "+f"(c[3])
        : "r"(a[0]), "r"(a[1]), "r"(a[2]), "r"(a[3]), "r"(b0), "r"(b1));
}

// ======================= small kernels =======================
__global__ void zero_norm_kernel() {
    g_norm[blockIdx.x * 256 + threadIdx.x] = 0.0f;
}

// W:[K,256] row-major -> per-32k-chunk images [256][32] bf16, 64B rows, XOR swz
__global__ void prep_w_kernel(const float* __restrict__ W,
                              uint16_t* __restrict__ hiA,
                              uint16_t* __restrict__ loA) {
    int idx = blockIdx.x * 256 + threadIdx.x;
    int k = idx >> 8, n = idx & 255;
    float v = W[(size_t)k * 256 + n];
    uint16_t h, l;
    bsplit(v, h, l);
    uint32_t off = (uint32_t)(k >> 5) * 16384u + (uint32_t)n * 64u +
                   (((uint32_t)(k & 31) * 2u) ^ ((uint32_t)(n & 7) << 3));
    hiA[off >> 1] = h;
    loA[off >> 1] = l;
}

__global__ void norm_kernel(const int* __restrict__ bidx, float* __restrict__ out) {
    int i = blockIdx.x * 256 + threadIdx.x;
    out[i] = out[i] / g_norm[bidx[i]];
}

// ======================= device sub-steps =======================
// copy 32KB weight chunk (16K hi + 16K lo) into stage chunk&1
__device__ __forceinline__ void issueB(uint32_t sb, int chunk,
                                       const uint16_t* hi, const uint16_t* lo,
                                       int tid) {
    uint32_t d = sb + (uint32_t)(chunk & 1) * 32768u;
    const char* sh = (const char*)hi + (size_t)chunk * 16384;
    const char* sl = (const char*)lo + (size_t)chunk * 16384;
    #pragma unroll
    for (int i = tid; i < 1024; i += NTHR) {
        cp16(d + i * 16, sh + i * 16);
        cp16(d + 16384 + i * 16, sl + i * 16);
    }
}

// cp.async raw fp32 A chunk (128 rows x 64 k) into staging (permuted 16B units)
__device__ __forceinline__ void issueA(uint32_t sb, int c64,
                                       const float* x, const float* gf,
                                       const int* sidx, int row0, int tid) {
    uint32_t stg = sb + H1_HI + (uint32_t)(c64 & 1) * 32768u;
    #pragma unroll
    for (int i = tid; i < 2048; i += NTHR) {
        int r = i >> 4, k = i & 15;
        const char* src = (c64 < 4)
            ? (const char*)(x + (size_t)(row0 + r) * DX + (c64 << 6)) + k * 16
            : (const char*)(gf + (size_t)sidx[r] * DG + ((c64 - 4) << 6)) + k * 16;
        uint32_t dst = stg + (uint32_t)(r * 256) + (uint32_t)((k >> 1) << 4) +
                       (uint32_t)((k & 1) << 7);
        cp16(dst, src);
    }
}

// fp32 staged -> bf16 hi/lo A image (128 rows x 64 k, 128B rows, XOR (r&7)<<4)
__device__ __forceinline__ void convertA(char* smc, int c64, int tid) {
    uint32_t stg = H1_HI + (uint32_t)(c64 & 1) * 32768u;
    #pragma unroll
    for (int t = 0; t < 2; t++) {
        int u = tid + t * NTHR;
        int r = u >> 3, q = u & 7;
        float4 fa = *(const float4*)(smc + stg + r * 256 + q * 16);
        float4 fb = *(const float4*)(smc + stg + r * 256 + q * 16 + 128);
        uint16_t h[8], l[8];
        bsplit(fa.x, h[0], l[0]); bsplit(fa.y, h[1], l[1]);
        bsplit(fa.z, h[2], l[2]); bsplit(fa.w, h[3], l[3]);
        bsplit(fb.x, h[4], l[4]); bsplit(fb.y, h[5], l[5]);
        bsplit(fb.z, h[6], l[6]); bsplit(fb.w, h[7], l[7]);
        uint32_t off = (uint32_t)(r * 128) + (((uint32_t)(q * 16)) ^ ((uint32_t)(r & 7) << 4));
        *(uint4*)(smc + A_HI + off) = make_uint4(
            (uint32_t)h[0] | ((uint32_t)h[1] << 16), (uint32_t)h[2] | ((uint32_t)h[3] << 16),
            (uint32_t)h[4] | ((uint32_t)h[5] << 16), (uint32_t)h[6] | ((uint32_t)h[7] << 16));
        *(uint4*)(smc + A_LO + off) = make_uint4(
            (uint32_t)l[0] | ((uint32_t)l[1] << 16), (uint32_t)l[2] | ((uint32_t)l[3] << 16),
            (uint32_t)l[4] | ((uint32_t)l[5] << 16), (uint32_t)l[6] | ((uint32_t)l[7] << 16));
    }
}

// ======================= main fused kernel =======================
__global__ __launch_bounds__(NTHR, 1) void att_kernel(
    const float* __restrict__ x, const int* __restrict__ bidx,
    const float* __restrict__ gf,
    const float* __restrict__ b0,
    const float* __restrict__ W2, const float* __restrict__ b2,
    const float* __restrict__ gamma0, const float* __restrict__ beta0,
    const float* __restrict__ mean0, const float* __restrict__ var0,
    const float* __restrict__ b1,
    const float* __restrict__ gamma1, const float* __restrict__ beta1,
    const float* __restrict__ mean1, const float* __restrict__ var1,
    float* __restrict__ out)
{
    extern __shared__ char smc[];
    const uint32_t sb = smem_u32(smc);
    const int tid = threadIdx.x;
    const int wid = tid >> 5;
    const int lane = tid & 31;
    const int row0 = blockIdx.x * MTILE;
    const int mw = wid >> 2;          // 0..3  M groups of 32
    const int nw = wid & 3;           // 0..3  N groups of 64
    const int qr = lane >> 2;         // 0..7
    const int qc = (lane & 3) * 4;    // k-pair byte offset

    int* sidx = (int*)(smc + SIDX);
    if (tid < MTILE) sidx[tid] = bidx[row0 + tid];

    // prologue prefetch: W0 chunk0 + A raw chunk0 (x only; no sidx needed)
    issueB(sb, 0, gW0hi, gW0lo, tid);
    issueA(sb, 0, x, gf, sidx, row0, tid);
    CP_COMMIT();

    float C[2][8][4];
    #pragma unroll
    for (int i = 0; i < 2; i++)
        #pragma unroll
        for (int j = 0; j < 8; j++)
            #pragma unroll
            for (int p = 0; p < 4; p++) C[i][j][p] = 0.0f;

    // =================== GEMM1: [128 x 384] @ W0 (12 x 32k chunks) ===================
    for (int cidx = 0; cidx < 12; cidx++) {
        const int c64 = cidx >> 1, h = cidx & 1;
        __syncthreads();                                  // prev MMA done
        if (cidx + 1 < 12) issueB(sb, cidx + 1, gW0hi, gW0lo, tid);
        if (h == 0 && c64 + 1 < 6) issueA(sb, c64 + 1, x, gf, sidx, row0, tid);
        CP_COMMIT();
        CP_WAIT1();
        __syncthreads();                                  // chunk cidx visible
        if (h == 0) { convertA(smc, c64, tid); __syncthreads(); }

        const uint32_t stb = (uint32_t)(cidx & 1) * 32768u;
        #pragma unroll
        for (int ks = 0; ks < 2; ks++) {
            const int ksa = h * 2 + ks;
            uint32_t ah[2][4], al[2][4];
            #pragma unroll
            for (int i = 0; i < 2; i++) {
                int r = mw * 32 + i * 16 + qr;
                uint32_t xr = (uint32_t)((r & 7) << 4);
                uint32_t base = (uint32_t)(r * 128);
                uint32_t o0 = ((uint32_t)(ksa * 32 + qc)) ^ xr;
                uint32_t o2 = ((uint32_t)(ksa * 32 + qc + 16)) ^ xr;
                ah[i][0] = *(const uint32_t*)(smc + A_HI + base + o0);
                ah[i][1] = *(const uint32_t*)(smc + A_HI + base + 1024 + o0);
                ah[i][2] = *(const uint32_t*)(smc + A_HI + base + o2);
                ah[i][3] = *(const uint32_t*)(smc + A_HI + base + 1024 + o2);
                al[i][0] = *(const uint32_t*)(smc + A_LO + base + o0);
                al[i][1] = *(const uint32_t*)(smc + A_LO + base + 1024 + o0);
                al[i][2] = *(const uint32_t*)(smc + A_LO + base + o2);
                al[i][3] = *(const uint32_t*)(smc + A_LO + base + 1024 + o2);
            }
            #pragma unroll
            for (int j = 0; j < 8; j++) {
                int n = nw * 64 + j * 8 + qr;
                uint32_t xb = (uint32_t)((n & 7) << 3);
                uint32_t bb = stb + (uint32_t)(n * 64);
                uint32_t o0 = ((uint32_t)(ks * 32 + qc)) ^ xb;
                uint32_t o1 = ((uint32_t)(ks * 32 + qc + 16)) ^ xb;
                uint32_t bh0 = *(const uint32_t*)(smc + bb + o0);
                uint32_t bh1 = *(const uint32_t*)(smc + bb + o1);
                uint32_t bl0 = *(const uint32_t*)(smc + bb + 16384 + o0);
                uint32_t bl1 = *(const uint32_t*)(smc + bb + 16384 + o1);
                #pragma unroll
                for (int i = 0; i < 2; i++) {
                    mma16816(C[i][j], ah[i], bh0, bh1);
                    mma16816(C[i][j], ah[i], bl0, bl1);
                    mma16816(C[i][j], al[i], bh0, bh1);
                }
            }
        }
    }
    __syncthreads();   // all GEMM1 MMAs done; stages + A region free

    // prefetch W1 chunk0 (overlaps epilogue 1), fold BN params into dead A region
    issueB(sb, 0, gW1hi, gW1lo, tid);
    CP_COMMIT();
    if (tid < 256) {
        int cc = tid;
        float s0v = gamma0[cc] * rsqrtf(var0[cc] + BN_EPS);
        ((float*)(smc + P_S0))[cc]  = s0v;
        ((float*)(smc + P_SH0))[cc] = fmaf(b0[cc] - mean0[cc], s0v, beta0[cc]);
        float s1v = gamma1[cc] * rsqrtf(var1[cc] + BN_EPS);
        ((float*)(smc + P_S1))[cc]  = s1v;
        ((float*)(smc + P_SH1))[cc] = fmaf(b1[cc] - mean1[cc], s1v, beta1[cc]);
        ((float*)(smc + P_W2))[cc]  = W2[cc];
    }
    __syncthreads();

    // ====== Epilogue 1: BN0+ReLU, bf16 split, write h1 [128][256] 512B rows ======
    {
        const float* sS0  = (const float*)(smc + P_S0);
        const float* sSH0 = (const float*)(smc + P_SH0);
        #pragma unroll
        for (int i = 0; i < 2; i++) {
            int r = mw * 32 + i * 16 + qr;
            uint32_t xr0 = (uint32_t)((r & 7) << 4);
            uint32_t rb0 = (uint32_t)(r * 512);
            uint32_t rb1 = (uint32_t)((r + 8) * 512);
            #pragma unroll
            for (int j = 0; j < 8; j++) {
                int col = nw * 64 + j * 8 + (lane & 3) * 2;
                float s0a = sS0[col], s0b = sS0[col + 1];
                float h0a = sSH0[col], h0b = sSH0[col + 1];
                float v00 = fmaxf(fmaf(C[i][j][0], s0a, h0a), 0.f);
                float v01 = fmaxf(fmaf(C[i][j][1], s0b, h0b), 0.f);
                float v10 = fmaxf(fmaf(C[i][j][2], s0a, h0a), 0.f);
                float v11 = fmaxf(fmaf(C[i][j][3], s0b, h0b), 0.f);
                uint16_t h00, l00, h01, l01, h10, l10, h11, l11;
                bsplit(v00, h00, l00); bsplit(v01, h01, l01);
                bsplit(v10, h10, l10); bsplit(v11, h11, l11);
                uint32_t ko = ((uint32_t)(col * 2)) ^ xr0;
                *(uint32_t*)(smc + H1_HI + rb0 + ko) = (uint32_t)h00 | ((uint32_t)h01 << 16);
                *(uint32_t*)(smc + H1_LO + rb0 + ko) = (uint32_t)l00 | ((uint32_t)l01 << 16);
                *(uint32_t*)(smc + H1_HI + rb1 + ko) = (uint32_t)h10 | ((uint32_t)h11 << 16);
                *(uint32_t*)(smc + H1_LO + rb1 + ko) = (uint32_t)l10 | ((uint32_t)l11 << 16);
            }
        }
    }

    #pragma unroll
    for (int i = 0; i < 2; i++)
        #pragma unroll
        for (int j = 0; j < 8; j++)
            #pragma unroll
            for (int p = 0; p < 4; p++) C[i][j][p] = 0.0f;

    // =================== GEMM2: h1 [128 x 256] @ W1 (8 x 32k chunks) ===================
    for (int cidx = 0; cidx < 8; cidx++) {
        __syncthreads();                                  // h1 visible / prev MMA done
        if (cidx + 1 < 8) issueB(sb, cidx + 1, gW1hi, gW1lo, tid);
        CP_COMMIT();
        CP_WAIT1();
        __syncthreads();

        const uint32_t stb = (uint32_t)(cidx & 1) * 32768u;
        #pragma unroll
        for (int ks = 0; ks < 2; ks++) {
            uint32_t ah[2][4], al[2][4];
            #pragma unroll
            for (int i = 0; i < 2; i++) {
                int r = mw * 32 + i * 16 + qr;
                uint32_t xr = (uint32_t)((r & 7) << 4);
                uint32_t base = (uint32_t)(r * 512);
                uint32_t o0 = ((uint32_t)((cidx * 2 + ks) * 32 + qc)) ^ xr;
                uint32_t o2 = ((uint32_t)((cidx * 2 + ks) * 32 + qc + 16)) ^ xr;
                ah[i][0] = *(const uint32_t*)(smc + H1_HI + base + o0);
                ah[i][1] = *(const uint32_t*)(smc + H1_HI + base + 4096 + o0);
                ah[i][2] = *(const uint32_t*)(smc + H1_HI + base + o2);
                ah[i][3] = *(const uint32_t*)(smc + H1_HI + base + 4096 + o2);
                al[i][0] = *(const uint32_t*)(smc + H1_LO + base + o0);
                al[i][1] = *(const uint32_t*)(smc + H1_LO + base + 4096 + o0);
                al[i][2] = *(const uint32_t*)(smc + H1_LO + base + o2);
                al[i][3] = *(const uint32_t*)(smc + H1_LO + base + 4096 + o2);
            }
            #pragma unroll
            for (int j = 0; j < 8; j++) {
                int n = nw * 64 + j * 8 + qr;
                uint32_t xb = (uint32_t)((n & 7) << 3);
                uint32_t bb = stb + (uint32_t)(n * 64);
                uint32_t o0 = ((uint32_t)(ks * 32 + qc)) ^ xb;
                uint32_t o1 = ((uint32_t)(ks * 32 + qc + 16)) ^ xb;
                uint32_t bh0 = *(const uint32_t*)(smc + bb + o0);
                uint32_t bh1 = *(const uint32_t*)(smc + bb + o1);
                uint32_t bl0 = *(const uint32_t*)(smc + bb + 16384 + o0);
                uint32_t bl1 = *(const uint32_t*)(smc + bb + 16384 + o1);
                #pragma unroll
                for (int i = 0; i < 2; i++) {
                    mma16816(C[i][j], ah[i], bh0, bh1);
                    mma16816(C[i][j], ah[i], bl0, bl1);
                    mma16816(C[i][j], al[i], bh0, bh1);
                }
            }
        }
    }
    CP_WAITALL();

    // ====== Epilogue 2: BN1+ReLU, dot W2, reduce, exp, segment atomics ======
    {
        const float* sS1  = (const float*)(smc + P_S1);
        const float* sSH1 = (const float*)(smc + P_SH1);
        const float* sW2  = (const float*)(smc + P_W2);
        float pl[2][2] = {{0.f, 0.f}, {0.f, 0.f}};
        #pragma unroll
        for (int i = 0; i < 2; i++) {
            #pragma unroll
            for (int j = 0; j < 8; j++) {
                int col = nw * 64 + j * 8 + (lane & 3) * 2;
                float s1a = sS1[col], s1b = sS1[col + 1];
                float h1a = sSH1[col], h1b = sSH1[col + 1];
                float w2a = sW2[col], w2b = sW2[col + 1];
                pl[i][0] = fmaf(fmaxf(fmaf(C[i][j][0], s1a, h1a), 0.f), w2a, pl[i][0]);
                pl[i][0] = fmaf(fmaxf(fmaf(C[i][j][1], s1b, h1b), 0.f), w2b, pl[i][0]);
                pl[i][1] = fmaf(fmaxf(fmaf(C[i][j][2], s1a, h1a), 0.f), w2a, pl[i][1]);
                pl[i][1] = fmaf(fmaxf(fmaf(C[i][j][3], s1b, h1b), 0.f), w2b, pl[i][1]);
            }
        }
        #pragma unroll
        for (int off = 1; off <= 2; off <<= 1)
            #pragma unroll
            for (int i = 0; i < 2; i++) {
                pl[i][0] += __shfl_xor_sync(0xffffffffu, pl[i][0], off);
                pl[i][1] += __shfl_xor_sync(0xffffffffu, pl[i][1], off);
            }
        float* part = (float*)(smc + PART);
        if ((lane & 3) == 0) {
            #pragma unroll
            for (int i = 0; i < 2; i++) {
                int r = mw * 32 + i * 16 + qr;
                part[nw * 128 + r]     = pl[i][0];
                part[nw * 128 + r + 8] = pl[i][1];
            }
        }
        __syncthreads();
        if (tid < MTILE) {
            float logit = part[tid] + part[128 + tid] + part[256 + tid] +
                          part[384 + tid] + b2[0];
            float av = expf(logit);
            out[row0 + tid] = av;
            atomicAdd(&g_norm[sidx[tid]], av);
        }
    }
}

// ======================= launch =======================
extern "C" void kernel_launch(void* const* d_in, const int* in_sizes, int n_in,
                              void* d_out, int out_size) {
    const float* x      = (const float*)d_in[0];
    const int*   bidx   = (const int*)  d_in[1];
    const float* gf     = (const float*)d_in[2];
    const float* W0     = (const float*)d_in[3];
    const float* b0     = (const float*)d_in[4];
    const float* W1     = (const float*)d_in[5];
    const float* b1     = (const float*)d_in[6];
    const float* W2     = (const float*)d_in[7];
    const float* b2     = (const float*)d_in[8];
    const float* gamma0 = (const float*)d_in[9];
    const float* beta0  = (const float*)d_in[10];
    const float* mean0  = (const float*)d_in[11];
    const float* var0   = (const float*)d_in[12];
    const float* gamma1 = (const float*)d_in[13];
    const float* beta1  = (const float*)d_in[14];
    const float* mean1  = (const float*)d_in[15];
    const float* var1   = (const float*)d_in[16];
    float* out = (float*)d_out;

    static uint16_t *pW0hi = nullptr, *pW0lo, *pW1hi, *pW1lo;
    if (!pW0hi) {
        cudaGetSymbolAddress((void**)&pW0hi, gW0hi);
        cudaGetSymbolAddress((void**)&pW0lo, gW0lo);
        cudaGetSymbolAddress((void**)&pW1hi, gW1hi);
        cudaGetSymbolAddress((void**)&pW1lo, gW1lo);
        cudaFuncSetAttribute(att_kernel, cudaFuncAttributeMaxDynamicSharedMemorySize,
                             SMEM_TOTAL);
    }

    prep_w_kernel<<<DIN, 256>>>(W0, pW0hi, pW0lo);
    prep_w_kernel<<<HID, 256>>>(W1, pW1hi, pW1lo);
    zero_norm_kernel<<<NG / 256, 256>>>();
    att_kernel<<<NCTA, NTHR, SMEM_TOTAL>>>(
        x, bidx, gf, b0, W2, b2,
        gamma0, beta0, mean0, var0,
        b1, gamma1, beta1, mean1, var1, out);
    norm_kernel<<<NN / 256, 256>>>(bidx, out);
}

// round 5
// speedup vs baseline: 4.1684x; 1.1719x over previous
#include <cuda_runtime.h>
#include <cuda_bf16.h>
#include <math.h>
#include <stdint.h>

#define NN   262144
#define NG   2048
#define DX   256
#define DG   128
#define DIN  384
#define HID  256
#define BN_EPS 1e-3f
#define MTILE 64
#define NCTA (NN / MTILE)
#define NTHR 256

// ---- smem byte map (112,896 B total; 2 CTAs/SM) ----
#define B_HI   0        // 16KB  B chunk hi  [256 n][32 k] bf16, 64B rows, XOR (n&7)<<3
#define B_LO   16384    // 16KB  B chunk lo
#define A_HI   32768    // 4KB   A img hi   [64 m][32 k]  bf16, 64B rows, XOR (m&7)<<3
#define A_LO   36864    // 4KB
#define H1_HI  40960    // 32KB  h1 hi [64 m][256 k] bf16, 512B rows, XOR (m&7)<<4
#define H1_LO  73728    // 32KB
#define P_S0   106496
#define P_SH0  107520
#define P_S1   108544
#define P_SH1  109568
#define P_W2   110592
#define SIDX   111616   // 256B
#define PART   111872   // 1KB float[4][64]
#define SMEM_TOTAL 112896

__device__ float g_norm[NG];
// pre-split, pre-transposed, pre-swizzled weight images:
// per 32-k chunk: [n=256][k=32] bf16, 64B rows, XOR (n&7)<<3
__device__ __align__(16) uint16_t gW0hi[12 * 8192];
__device__ __align__(16) uint16_t gW0lo[12 * 8192];
__device__ __align__(16) uint16_t gW1hi[8 * 8192];
__device__ __align__(16) uint16_t gW1lo[8 * 8192];

// ======================= helpers =======================
__device__ __forceinline__ uint32_t smem_u32(const void* p) {
    uint32_t a;
    asm("{ .reg .u64 t; cvta.to.shared.u64 t, %1; cvt.u32.u64 %0, t; }"
        : "=r"(a) : "l"(p));
    return a;
}
__device__ __forceinline__ void cp16(uint32_t dst, const void* src) {
    asm volatile("cp.async.cg.shared.global [%0], [%1], 16;"
                 :: "r"(dst), "l"(__cvta_generic_to_global(src)) : "memory");
}
#define CP_COMMIT()  asm volatile("cp.async.commit_group;" ::: "memory")
#define CP_WAITALL() asm volatile("cp.async.wait_all;" ::: "memory")

__device__ __forceinline__ void bsplit(float f, uint16_t& h, uint16_t& l) {
    __nv_bfloat16 hb = __float2bfloat16(f);
    __nv_bfloat16 lb = __float2bfloat16(f - __bfloat162float(hb));
    h = __bfloat16_as_ushort(hb);
    l = __bfloat16_as_ushort(lb);
}
__device__ __forceinline__ void mma16816(float* c, const uint32_t* a,
                                         uint32_t b0, uint32_t b1) {
    asm volatile(
        "mma.sync.aligned.m16n8k16.row.col.f32.bf16.bf16.f32 "
        "{%0,%1,%2,%3}, {%4,%5,%6,%7}, {%8,%9}, {%0,%1,%2,%3};"
        : "+f"(c[0]), "+f"(c[1]), "+f"(c[2]), "+f"(c[3])
        : "r"(a[0]), "r"(a[1]), "r"(a[2]), "r"(a[3]), "r"(b0), "r"(b1));
}

// ======================= small kernels =======================
__global__ void zero_norm_kernel() {
    g_norm[blockIdx.x * 256 + threadIdx.x] = 0.0f;
}

// W:[K,256] row-major -> per-32k-chunk images [256][32] bf16, 64B rows, XOR swz
__global__ void prep_w_kernel(const float* __restrict__ W,
                              uint16_t* __restrict__ hiA,
                              uint16_t* __restrict__ loA) {
    int idx = blockIdx.x * 256 + threadIdx.x;
    int k = idx >> 8, n = idx & 255;
    float v = W[(size_t)k * 256 + n];
    uint16_t h, l;
    bsplit(v, h, l);
    uint32_t off = (uint32_t)(k >> 5) * 16384u + (uint32_t)n * 64u +
                   (((uint32_t)(k & 31) * 2u) ^ ((uint32_t)(n & 7) << 3));
    hiA[off >> 1] = h;
    loA[off >> 1] = l;
}

__global__ void norm_kernel(const int* __restrict__ bidx, float* __restrict__ out) {
    int i = blockIdx.x * 256 + threadIdx.x;
    out[i] = out[i] / g_norm[bidx[i]];
}

// ======================= device sub-steps =======================
// cp.async one 32KB weight chunk (16K hi + 16K lo) into the single B stage
__device__ __forceinline__ void issueB(uint32_t sb, int chunk,
                                       const uint16_t* hi, const uint16_t* lo,
                                       int tid) {
    const char* sh = (const char*)hi + (size_t)chunk * 16384;
    const char* sl = (const char*)lo + (size_t)chunk * 16384;
    #pragma unroll
    for (int i = tid; i < 1024; i += NTHR) {
        cp16(sb + B_HI + i * 16, sh + i * 16);
        cp16(sb + B_LO + i * 16, sl + i * 16);
    }
}

// gmem fp32 -> bf16 hi/lo A image for 32-k chunk cidx (64 rows x 32 k)
__device__ __forceinline__ void convertA32(char* smc, int cidx,
                                           const float* x, const float* gf,
                                           const int* sidx, int row0, int tid) {
    #pragma unroll
    for (int t = 0; t < 2; t++) {
        int u = tid + t * NTHR;           // 0..511
        int r = u >> 3, q = u & 7;        // row 0..63, float4 idx 0..7
        const float* src = (cidx < 8)
            ? (x + (size_t)(row0 + r) * DX + cidx * 32 + q * 4)
            : (gf + (size_t)sidx[r] * DG + (cidx - 8) * 32 + q * 4);
        float4 f = *(const float4*)src;
        uint16_t h0, l0, h1, l1, h2, l2, h3, l3;
        bsplit(f.x, h0, l0); bsplit(f.y, h1, l1);
        bsplit(f.z, h2, l2); bsplit(f.w, h3, l3);
        uint32_t off = (uint32_t)(r * 64) + (((uint32_t)(q * 8)) ^ ((uint32_t)(r & 7) << 3));
        *(uint2*)(smc + A_HI + off) = make_uint2(
            (uint32_t)h0 | ((uint32_t)h1 << 16), (uint32_t)h2 | ((uint32_t)h3 << 16));
        *(uint2*)(smc + A_LO + off) = make_uint2(
            (uint32_t)l0 | ((uint32_t)l1 << 16), (uint32_t)l2 | ((uint32_t)l3 << 16));
    }
}

// ======================= main fused kernel =======================
__global__ __launch_bounds__(NTHR, 2) void att_kernel(
    const float* __restrict__ x, const int* __restrict__ bidx,
    const float* __restrict__ gf,
    const float* __restrict__ b0,
    const float* __restrict__ W2, const float* __restrict__ b2,
    const float* __restrict__ gamma0, const float* __restrict__ beta0,
    const float* __restrict__ mean0, const float* __restrict__ var0,
    const float* __restrict__ b1,
    const float* __restrict__ gamma1, const float* __restrict__ beta1,
    const float* __restrict__ mean1, const float* __restrict__ var1,
    float* __restrict__ out)
{
    extern __shared__ char smc[];
    const uint32_t sb = smem_u32(smc);
    const int tid = threadIdx.x;
    const int wid = tid >> 5;
    const int lane = tid & 31;
    const int row0 = blockIdx.x * MTILE;
    const int mw = wid >> 2;          // 0..1  M groups of 32
    const int nw = wid & 3;           // 0..3  N groups of 64
    const int qr = lane >> 2;         // 0..7
    const int qc = (lane & 3) * 4;    // k-pair byte offset

    int* sidx = (int*)(smc + SIDX);
    if (tid < MTILE) sidx[tid] = bidx[row0 + tid];
    // fold BN params
    {
        int cc = tid;
        float s0v = gamma0[cc] * rsqrtf(var0[cc] + BN_EPS);
        ((float*)(smc + P_S0))[cc]  = s0v;
        ((float*)(smc + P_SH0))[cc] = fmaf(b0[cc] - mean0[cc], s0v, beta0[cc]);
        float s1v = gamma1[cc] * rsqrtf(var1[cc] + BN_EPS);
        ((float*)(smc + P_S1))[cc]  = s1v;
        ((float*)(smc + P_SH1))[cc] = fmaf(b1[cc] - mean1[cc], s1v, beta1[cc]);
        ((float*)(smc + P_W2))[cc]  = W2[cc];
    }
    __syncthreads();

    float C[2][8][4];
    #pragma unroll
    for (int i = 0; i < 2; i++)
        #pragma unroll
        for (int j = 0; j < 8; j++)
            #pragma unroll
            for (int p = 0; p < 4; p++) C[i][j][p] = 0.0f;

    // =================== GEMM1: [64 x 384] @ W0 (12 x 32k chunks) ===================
    for (int cidx = 0; cidx < 12; cidx++) {
        if (cidx) __syncthreads();                 // prior MMA done with B/A img
        issueB(sb, cidx, gW0hi, gW0lo, tid);
        CP_COMMIT();
        convertA32(smc, cidx, x, gf, sidx, row0, tid);   // overlaps B copy
        CP_WAITALL();
        __syncthreads();

        #pragma unroll
        for (int ks = 0; ks < 2; ks++) {
            uint32_t ah[2][4], al[2][4];
            #pragma unroll
            for (int i = 0; i < 2; i++) {
                int r = mw * 32 + i * 16 + qr;
                uint32_t xr = (uint32_t)(qr << 3);
                uint32_t base = (uint32_t)(r * 64);
                uint32_t o0 = ((uint32_t)(ks * 32 + qc)) ^ xr;
                uint32_t o2 = ((uint32_t)(ks * 32 + qc + 16)) ^ xr;
                ah[i][0] = *(const uint32_t*)(smc + A_HI + base + o0);
                ah[i][1] = *(const uint32_t*)(smc + A_HI + base + 512 + o0);
                ah[i][2] = *(const uint32_t*)(smc + A_HI + base + o2);
                ah[i][3] = *(const uint32_t*)(smc + A_HI + base + 512 + o2);
                al[i][0] = *(const uint32_t*)(smc + A_LO + base + o0);
                al[i][1] = *(const uint32_t*)(smc + A_LO + base + 512 + o0);
                al[i][2] = *(const uint32_t*)(smc + A_LO + base + o2);
                al[i][3] = *(const uint32_t*)(smc + A_LO + base + 512 + o2);
            }
            #pragma unroll
            for (int j = 0; j < 8; j++) {
                int n = nw * 64 + j * 8 + qr;
                uint32_t xb = (uint32_t)(qr << 3);
                uint32_t bb = (uint32_t)(n * 64);
                uint32_t o0 = ((uint32_t)(ks * 32 + qc)) ^ xb;
                uint32_t o1 = ((uint32_t)(ks * 32 + qc + 16)) ^ xb;
                uint32_t bh0 = *(const uint32_t*)(smc + B_HI + bb + o0);
                uint32_t bh1 = *(const uint32_t*)(smc + B_HI + bb + o1);
                uint32_t bl0 = *(const uint32_t*)(smc + B_LO + bb + o0);
                uint32_t bl1 = *(const uint32_t*)(smc + B_LO + bb + o1);
                #pragma unroll
                for (int i = 0; i < 2; i++) {
                    mma16816(C[i][j], ah[i], bh0, bh1);
                    mma16816(C[i][j], ah[i], bl0, bl1);
                    mma16816(C[i][j], al[i], bh0, bh1);
                }
            }
        }
    }

    // ====== Epilogue 1: BN0+ReLU, bf16 split, write h1 [64][256] 512B rows ======
    // (h1 region untouched during GEMM1; only own C regs read — no sync needed)
    {
        const float* sS0  = (const float*)(smc + P_S0);
        const float* sSH0 = (const float*)(smc + P_SH0);
        #pragma unroll
        for (int i = 0; i < 2; i++) {
            int r = mw * 32 + i * 16 + qr;
            uint32_t xr0 = (uint32_t)(qr << 4);
            uint32_t rb0 = (uint32_t)(r * 512);
            uint32_t rb1 = (uint32_t)((r + 8) * 512);
            #pragma unroll
            for (int j = 0; j < 8; j++) {
                int col = nw * 64 + j * 8 + (lane & 3) * 2;
                float s0a = sS0[col], s0b = sS0[col + 1];
                float h0a = sSH0[col], h0b = sSH0[col + 1];
                float v00 = fmaxf(fmaf(C[i][j][0], s0a, h0a), 0.f);
                float v01 = fmaxf(fmaf(C[i][j][1], s0b, h0b), 0.f);
                float v10 = fmaxf(fmaf(C[i][j][2], s0a, h0a), 0.f);
                float v11 = fmaxf(fmaf(C[i][j][3], s0b, h0b), 0.f);
                uint16_t h00, l00, h01, l01, h10, l10, h11, l11;
                bsplit(v00, h00, l00); bsplit(v01, h01, l01);
                bsplit(v10, h10, l10); bsplit(v11, h11, l11);
                uint32_t ko = ((uint32_t)(col * 2)) ^ xr0;
                *(uint32_t*)(smc + H1_HI + rb0 + ko) = (uint32_t)h00 | ((uint32_t)h01 << 16);
                *(uint32_t*)(smc + H1_LO + rb0 + ko) = (uint32_t)l00 | ((uint32_t)l01 << 16);
                *(uint32_t*)(smc + H1_HI + rb1 + ko) = (uint32_t)h10 | ((uint32_t)h11 << 16);
                *(uint32_t*)(smc + H1_LO + rb1 + ko) = (uint32_t)l10 | ((uint32_t)l11 << 16);
            }
        }
    }

    #pragma unroll
    for (int i = 0; i < 2; i++)
        #pragma unroll
        for (int j = 0; j < 8; j++)
            #pragma unroll
            for (int p = 0; p < 4; p++) C[i][j][p] = 0.0f;

    // =================== GEMM2: h1 [64 x 256] @ W1 (8 x 32k chunks) ===================
    for (int cidx = 0; cidx < 8; cidx++) {
        __syncthreads();                  // h1 visible (c=0) / prior MMA done with B
        issueB(sb, cidx, gW1hi, gW1lo, tid);
        CP_COMMIT();
        CP_WAITALL();
        __syncthreads();

        #pragma unroll
        for (int ks = 0; ks < 2; ks++) {
            uint32_t ah[2][4], al[2][4];
            #pragma unroll
            for (int i = 0; i < 2; i++) {
                int r = mw * 32 + i * 16 + qr;
                uint32_t xr = (uint32_t)(qr << 4);
                uint32_t base = (uint32_t)(r * 512);
                uint32_t o0 = ((uint32_t)((cidx * 2 + ks) * 32 + qc)) ^ xr;
                uint32_t o2 = ((uint32_t)((cidx * 2 + ks) * 32 + qc + 16)) ^ xr;
                ah[i][0] = *(const uint32_t*)(smc + H1_HI + base + o0);
                ah[i][1] = *(const uint32_t*)(smc + H1_HI + base + 4096 + o0);
                ah[i][2] = *(const uint32_t*)(smc + H1_HI + base + o2);
                ah[i][3] = *(const uint32_t*)(smc + H1_HI + base + 4096 + o2);
                al[i][0] = *(const uint32_t*)(smc + H1_LO + base + o0);
                al[i][1] = *(const uint32_t*)(smc + H1_LO + base + 4096 + o0);
                al[i][2] = *(const uint32_t*)(smc + H1_LO + base + o2);
                al[i][3] = *(const uint32_t*)(smc + H1_LO + base + 4096 + o2);
            }
            #pragma unroll
            for (int j = 0; j < 8; j++) {
                int n = nw * 64 + j * 8 + qr;
                uint32_t xb = (uint32_t)(qr << 3);
                uint32_t bb = (uint32_t)(n * 64);
                uint32_t o0 = ((uint32_t)(ks * 32 + qc)) ^ xb;
                uint32_t o1 = ((uint32_t)(ks * 32 + qc + 16)) ^ xb;
                uint32_t bh0 = *(const uint32_t*)(smc + B_HI + bb + o0);
                uint32_t bh1 = *(const uint32_t*)(smc + B_HI + bb + o1);
                uint32_t bl0 = *(const uint32_t*)(smc + B_LO + bb + o0);
                uint32_t bl1 = *(const uint32_t*)(smc + B_LO + bb + o1);
                #pragma unroll
                for (int i = 0; i < 2; i++) {
                    mma16816(C[i][j], ah[i], bh0, bh1);
                    mma16816(C[i][j], ah[i], bl0, bl1);
                    mma16816(C[i][j], al[i], bh0, bh1);
                }
            }
        }
    }

    // ====== Epilogue 2: BN1+ReLU, dot W2, reduce, exp, segment atomics ======
    {
        const float* sS1  = (const float*)(smc + P_S1);
        const float* sSH1 = (const float*)(smc + P_SH1);
        const float* sW2  = (const float*)(smc + P_W2);
        float pl[2][2] = {{0.f, 0.f}, {0.f, 0.f}};
        #pragma unroll
        for (int i = 0; i < 2; i++) {
            #pragma unroll
            for (int j = 0; j < 8; j++) {
                int col = nw * 64 + j * 8 + (lane & 3) * 2;
                float s1a = sS1[col], s1b = sS1[col + 1];
                float h1a = sSH1[col], h1b = sSH1[col + 1];
                float w2a = sW2[col], w2b = sW2[col + 1];
                pl[i][0] = fmaf(fmaxf(fmaf(C[i][j][0], s1a, h1a), 0.f), w2a, pl[i][0]);
                pl[i][0] = fmaf(fmaxf(fmaf(C[i][j][1], s1b, h1b), 0.f), w2b, pl[i][0]);
                pl[i][1] = fmaf(fmaxf(fmaf(C[i][j][2], s1a, h1a), 0.f), w2a, pl[i][1]);
                pl[i][1] = fmaf(fmaxf(fmaf(C[i][j][3], s1b, h1b), 0.f), w2b, pl[i][1]);
            }
        }
        #pragma unroll
        for (int off = 1; off <= 2; off <<= 1)
            #pragma unroll
            for (int i = 0; i < 2; i++) {
                pl[i][0] += __shfl_xor_sync(0xffffffffu, pl[i][0], off);
                pl[i][1] += __shfl_xor_sync(0xffffffffu, pl[i][1], off);
            }
        float* part = (float*)(smc + PART);
        if ((lane & 3) == 0) {
            #pragma unroll
            for (int i = 0; i < 2; i++) {
                int r = mw * 32 + i * 16 + qr;
                part[nw * 64 + r]     = pl[i][0];
                part[nw * 64 + r + 8] = pl[i][1];
            }
        }
        __syncthreads();
        if (tid < MTILE) {
            float logit = part[tid] + part[64 + tid] + part[128 + tid] +
                          part[192 + tid] + b2[0];
            float av = expf(logit);
            out[row0 + tid] = av;
            atomicAdd(&g_norm[sidx[tid]], av);
        }
    }
}

// ======================= launch =======================
extern "C" void kernel_launch(void* const* d_in, const int* in_sizes, int n_in,
                              void* d_out, int out_size) {
    const float* x      = (const float*)d_in[0];
    const int*   bidx   = (const int*)  d_in[1];
    const float* gf     = (const float*)d_in[2];
    const float* W0     = (const float*)d_in[3];
    const float* b0     = (const float*)d_in[4];
    const float* W1     = (const float*)d_in[5];
    const float* b1     = (const float*)d_in[6];
    const float* W2     = (const float*)d_in[7];
    const float* b2     = (const float*)d_in[8];
    const float* gamma0 = (const float*)d_in[9];
    const float* beta0  = (const float*)d_in[10];
    const float* mean0  = (const float*)d_in[11];
    const float* var0   = (const float*)d_in[12];
    const float* gamma1 = (const float*)d_in[13];
    const float* beta1  = (const float*)d_in[14];
    const float* mean1  = (const float*)d_in[15];
    const float* var1   = (const float*)d_in[16];
    float* out = (float*)d_out;

    static uint16_t *pW0hi = nullptr, *pW0lo, *pW1hi, *pW1lo;
    if (!pW0hi) {
        cudaGetSymbolAddress((void**)&pW0hi, gW0hi);
        cudaGetSymbolAddress((void**)&pW0lo, gW0lo);
        cudaGetSymbolAddress((void**)&pW1hi, gW1hi);
        cudaGetSymbolAddress((void**)&pW1lo, gW1lo);
        cudaFuncSetAttribute(att_kernel, cudaFuncAttributeMaxDynamicSharedMemorySize,
                             SMEM_TOTAL);
    }

    prep_w_kernel<<<DIN, 256>>>(W0, pW0hi, pW0lo);
    prep_w_kernel<<<HID, 256>>>(W1, pW1hi, pW1lo);
    zero_norm_kernel<<<NG / 256, 256>>>();
    att_kernel<<<NCTA, NTHR, SMEM_TOTAL>>>(
        x, bidx, gf, b0, W2, b2,
        gamma0, beta0, mean0, var0,
        b1, gamma1, beta1, mean1, var1, out);
    norm_kernel<<<NN / 256, 256>>>(bidx, out);
}

// round 6
// speedup vs baseline: 4.2984x; 1.0312x over previous
#include <cuda_runtime.h>
#include <cuda_bf16.h>
#include <math.h>
#include <stdint.h>

#define NN   262144
#define NG   2048
#define DX   256
#define DG   128
#define DIN  384
#define HID  256
#define BN_EPS 1e-3f
#define MTILE 64
#define NCTA (NN / MTILE)
#define NTHR 256

// ---- smem byte map (104,704 B per CTA; 2 CTAs/SM) ----
// B stages: stage s @ s*16384 (hi 8KB @ +0, lo 8KB @ +8192); 32KB total
#define ABUF   32768    // A dbl-buf images (inside h1 region, GEMM1 only): buf p @ +p*4096 (hi 2K, lo 2K)
#define H1H    32768    // h1 hi [64 m][256 k] bf16, 512B rows, XOR (r&7)<<4 ; 32KB
#define H1L    65536    // h1 lo ; 32KB
#define P_S0   98304
#define P_SH0  99328
#define P_S1   100352
#define P_SH1  101376
#define P_W2   102400
#define SIDX   103424   // 256B
#define PART   103680   // 1KB float[4][64]
#define SMEM_TOTAL 104704

__device__ float g_norm[NG];
// pre-split, pre-transposed, pre-swizzled weight images:
// per 16-k chunk: [n=256][k=16] bf16 = 8KB, 32B rows, XOR (n&4)<<2
__device__ __align__(16) uint16_t gW0hi[24 * 4096];
__device__ __align__(16) uint16_t gW0lo[24 * 4096];
__device__ __align__(16) uint16_t gW1hi[16 * 4096];
__device__ __align__(16) uint16_t gW1lo[16 * 4096];

// ======================= helpers =======================
__device__ __forceinline__ uint32_t smem_u32(const void* p) {
    uint32_t a;
    asm("{ .reg .u64 t; cvta.to.shared.u64 t, %1; cvt.u32.u64 %0, t; }"
        : "=r"(a) : "l"(p));
    return a;
}
__device__ __forceinline__ void cp16(uint32_t dst, const void* src) {
    asm volatile("cp.async.cg.shared.global [%0], [%1], 16;"
                 :: "r"(dst), "l"(__cvta_generic_to_global(src)) : "memory");
}
#define CP_COMMIT() asm volatile("cp.async.commit_group;" ::: "memory")
#define CP_WAIT0()  asm volatile("cp.async.wait_group 0;" ::: "memory")
#define CP_WAIT1()  asm volatile("cp.async.wait_group 1;" ::: "memory")

__device__ __forceinline__ void bsplit(float f, uint16_t& h, uint16_t& l) {
    __nv_bfloat16 hb = __float2bfloat16(f);
    __nv_bfloat16 lb = __float2bfloat16(f - __bfloat162float(hb));
    h = __bfloat16_as_ushort(hb);
    l = __bfloat16_as_ushort(lb);
}
__device__ __forceinline__ void mma16816(float* c, const uint32_t* a,
                                         uint32_t b0, uint32_t b1) {
    asm volatile(
        "mma.sync.aligned.m16n8k16.row.col.f32.bf16.bf16.f32 "
        "{%0,%1,%2,%3}, {%4,%5,%6,%7}, {%8,%9}, {%0,%1,%2,%3};"
        : "+f"(c[0]), "+f"(c[1]), "+f"(c[2]), "+f"(c[3])
        : "r"(a[0]), "r"(a[1]), "r"(a[2]), "r"(a[3]), "r"(b0), "r"(b1));
}

// ======================= small kernels =======================
__global__ void zero_norm_kernel() {
    g_norm[blockIdx.x * 256 + threadIdx.x] = 0.0f;
}

// W:[K,256] row-major -> per-16k-chunk images [256][16] bf16, 32B rows, XOR (n&4)<<2
__global__ void prep_w_kernel(const float* __restrict__ W,
                              uint16_t* __restrict__ hiA,
                              uint16_t* __restrict__ loA) {
    int idx = blockIdx.x * 256 + threadIdx.x;
    int k = idx >> 8, n = idx & 255;
    float v = W[(size_t)k * 256 + n];
    uint16_t h, l;
    bsplit(v, h, l);
    uint32_t off = (uint32_t)(k >> 4) * 8192u + (uint32_t)n * 32u +
                   (((uint32_t)(k & 15) * 2u) ^ ((uint32_t)(n & 4) << 2));
    hiA[off >> 1] = h;
    loA[off >> 1] = l;
}

__global__ void norm_kernel(const int* __restrict__ bidx, float* __restrict__ out) {
    int i = blockIdx.x * 256 + threadIdx.x;
    out[i] = out[i] / g_norm[bidx[i]];
}

// ======================= device sub-steps =======================
// cp.async one 16KB weight chunk (8K hi + 8K lo) into stage g&1
__device__ __forceinline__ void issueB16(uint32_t sb, int g, int tid) {
    const uint16_t* hi = (g < 24) ? (gW0hi + g * 4096) : (gW1hi + (g - 24) * 4096);
    const uint16_t* lo = (g < 24) ? (gW0lo + g * 4096) : (gW1lo + (g - 24) * 4096);
    uint32_t d = sb + (uint32_t)(g & 1) * 16384u;
    #pragma unroll
    for (int i = tid; i < 512; i += NTHR) {
        cp16(d + i * 16, (const char*)hi + i * 16);
        cp16(d + 8192 + i * 16, (const char*)lo + i * 16);
    }
}

__device__ __forceinline__ float4 ldgA16(int c, const float* x, const float* gf,
                                         const int* sidx, int row0, int tid) {
    int r = tid >> 2, q = tid & 3;
    const float* src = (c < 16)
        ? (x + (size_t)(row0 + r) * DX + c * 16 + q * 4)
        : (gf + (size_t)sidx[r] * DG + (c - 16) * 16 + q * 4);
    return *(const float4*)src;
}

__device__ __forceinline__ void stsA16(char* smc, int p, float4 f, int tid) {
    int r = tid >> 2, q = tid & 3;
    uint16_t h0, l0, h1, l1, h2, l2, h3, l3;
    bsplit(f.x, h0, l0); bsplit(f.y, h1, l1);
    bsplit(f.z, h2, l2); bsplit(f.w, h3, l3);
    uint32_t off = (uint32_t)(r * 32) + (((uint32_t)(q * 8)) ^ ((uint32_t)(r & 4) << 2));
    uint32_t base = ABUF + (uint32_t)p * 4096u;
    *(uint2*)(smc + base + off) =
        make_uint2((uint32_t)h0 | ((uint32_t)h1 << 16), (uint32_t)h2 | ((uint32_t)h3 << 16));
    *(uint2*)(smc + base + 2048 + off) =
        make_uint2((uint32_t)l0 | ((uint32_t)l1 << 16), (uint32_t)l2 | ((uint32_t)l3 << 16));
}

// ======================= main fused kernel =======================
__global__ __launch_bounds__(NTHR, 2) void att_kernel(
    const float* __restrict__ x, const int* __restrict__ bidx,
    const float* __restrict__ gf,
    const float* __restrict__ b0,
    const float* __restrict__ W2, const float* __restrict__ b2,
    const float* __restrict__ gamma0, const float* __restrict__ beta0,
    const float* __restrict__ mean0, const float* __restrict__ var0,
    const float* __restrict__ b1,
    const float* __restrict__ gamma1, const float* __restrict__ beta1,
    const float* __restrict__ mean1, const float* __restrict__ var1,
    float* __restrict__ out)
{
    extern __shared__ char smc[];
    const uint32_t sb = smem_u32(smc);
    const int tid = threadIdx.x;
    const int wid = tid >> 5;
    const int lane = tid & 31;
    const int row0 = blockIdx.x * MTILE;
    const int mw = wid >> 2;          // 0..1  M groups of 32
    const int nw = wid & 3;           // 0..3  N groups of 64
    const int qr = lane >> 2;         // 0..7
    const int qc = (lane & 3) * 4;    // k-pair byte offset

    int* sidx = (int*)(smc + SIDX);
    if (tid < MTILE) sidx[tid] = bidx[row0 + tid];
    {   // fold BN params (256 threads = 256 cols)
        int cc = tid;
        float s0v = gamma0[cc] * rsqrtf(var0[cc] + BN_EPS);
        ((float*)(smc + P_S0))[cc]  = s0v;
        ((float*)(smc + P_SH0))[cc] = fmaf(b0[cc] - mean0[cc], s0v, beta0[cc]);
        float s1v = gamma1[cc] * rsqrtf(var1[cc] + BN_EPS);
        ((float*)(smc + P_S1))[cc]  = s1v;
        ((float*)(smc + P_SH1))[cc] = fmaf(b1[cc] - mean1[cc], s1v, beta1[cc]);
        ((float*)(smc + P_W2))[cc]  = W2[cc];
    }

    // prologue: stage W0 c0+c1, convert A(0)
    issueB16(sb, 0, tid); CP_COMMIT();
    issueB16(sb, 1, tid); CP_COMMIT();
    {
        float4 f0 = ldgA16(0, x, gf, sidx, row0, tid);   // c0 < 16: no sidx use
        stsA16(smc, 0, f0, tid);
    }
    CP_WAIT1();          // c0 landed
    __syncthreads();     // A(0), params, sidx visible

    float C[2][8][4];
    #pragma unroll
    for (int i = 0; i < 2; i++)
        #pragma unroll
        for (int j = 0; j < 8; j++)
            #pragma unroll
            for (int p = 0; p < 4; p++) C[i][j][p] = 0.0f;

    // =================== GEMM1: [64 x 384] @ W0 (24 x 16k chunks) ===================
    for (int i = 0; i < 24; i++) {
        float4 fA;
        if (i + 1 < 24) fA = ldgA16(i + 1, x, gf, sidx, row0, tid);

        {   // MMA(i): stage i&1, abuf i&1
            const uint32_t bs = (uint32_t)(i & 1) * 16384u;
            const uint32_t ab = ABUF + (uint32_t)(i & 1) * 4096u;
            uint32_t ah[2][4], al[2][4];
            #pragma unroll
            for (int m = 0; m < 2; m++) {
                int r = mw * 32 + m * 16 + qr;
                uint32_t xr = (uint32_t)((r & 4) << 2);
                uint32_t base = ab + (uint32_t)(r * 32);
                uint32_t o0 = ((uint32_t)qc) ^ xr;
                uint32_t o2 = ((uint32_t)(qc + 16)) ^ xr;
                ah[m][0] = *(const uint32_t*)(smc + base + o0);
                ah[m][1] = *(const uint32_t*)(smc + base + 256 + o0);
                ah[m][2] = *(const uint32_t*)(smc + base + o2);
                ah[m][3] = *(const uint32_t*)(smc + base + 256 + o2);
                al[m][0] = *(const uint32_t*)(smc + base + 2048 + o0);
                al[m][1] = *(const uint32_t*)(smc + base + 2304 + o0);
                al[m][2] = *(const uint32_t*)(smc + base + 2048 + o2);
                al[m][3] = *(const uint32_t*)(smc + base + 2304 + o2);
            }
            #pragma unroll
            for (int j = 0; j < 8; j++) {
                int n = nw * 64 + j * 8 + qr;
                uint32_t xn = (uint32_t)((n & 4) << 2);
                uint32_t bb = bs + (uint32_t)(n * 32);
                uint32_t o0 = ((uint32_t)qc) ^ xn;
                uint32_t o1 = ((uint32_t)(qc + 16)) ^ xn;
                uint32_t bh0 = *(const uint32_t*)(smc + bb + o0);
                uint32_t bh1 = *(const uint32_t*)(smc + bb + o1);
                uint32_t bl0 = *(const uint32_t*)(smc + bb + 8192 + o0);
                uint32_t bl1 = *(const uint32_t*)(smc + bb + 8192 + o1);
                #pragma unroll
                for (int m = 0; m < 2; m++) {
                    mma16816(C[m][j], ah[m], bh0, bh1);
                    mma16816(C[m][j], ah[m], bl0, bl1);
                    mma16816(C[m][j], al[m], bh0, bh1);
                }
            }
        }

        if (i + 1 < 24) stsA16(smc, (i + 1) & 1, fA, tid);
        CP_WAIT0();          // B chunk i+1 landed
        __syncthreads();     // A(i+1) visible; stage i&1 free
        issueB16(sb, i + 2, tid);   // i+2 <= 25 -> W1 c0/c1 at the tail
        CP_COMMIT();
    }

    // ====== Epilogue 1: BN0+ReLU, bf16 split, write h1 (overlaps W1 c1 copy) ======
    {
        const float* sS0  = (const float*)(smc + P_S0);
        const float* sSH0 = (const float*)(smc + P_SH0);
        #pragma unroll
        for (int m = 0; m < 2; m++) {
            int r = mw * 32 + m * 16 + qr;
            uint32_t xr0 = (uint32_t)(qr << 4);
            uint32_t rb0 = (uint32_t)(r * 512);
            uint32_t rb1 = (uint32_t)((r + 8) * 512);
            #pragma unroll
            for (int j = 0; j < 8; j++) {
                int col = nw * 64 + j * 8 + (lane & 3) * 2;
                float s0a = sS0[col], s0b = sS0[col + 1];
                float h0a = sSH0[col], h0b = sSH0[col + 1];
                float v00 = fmaxf(fmaf(C[m][j][0], s0a, h0a), 0.f);
                float v01 = fmaxf(fmaf(C[m][j][1], s0b, h0b), 0.f);
                float v10 = fmaxf(fmaf(C[m][j][2], s0a, h0a), 0.f);
                float v11 = fmaxf(fmaf(C[m][j][3], s0b, h0b), 0.f);
                uint16_t h00, l00, h01, l01, h10, l10, h11, l11;
                bsplit(v00, h00, l00); bsplit(v01, h01, l01);
                bsplit(v10, h10, l10); bsplit(v11, h11, l11);
                uint32_t ko = ((uint32_t)(col * 2)) ^ xr0;
                *(uint32_t*)(smc + H1H + rb0 + ko) = (uint32_t)h00 | ((uint32_t)h01 << 16);
                *(uint32_t*)(smc + H1L + rb0 + ko) = (uint32_t)l00 | ((uint32_t)l01 << 16);
                *(uint32_t*)(smc + H1H + rb1 + ko) = (uint32_t)h10 | ((uint32_t)h11 << 16);
                *(uint32_t*)(smc + H1L + rb1 + ko) = (uint32_t)l10 | ((uint32_t)l11 << 16);
            }
        }
    }
    CP_WAIT0();          // W1 c1 landed
    __syncthreads();     // h1 visible

    #pragma unroll
    for (int i = 0; i < 2; i++)
        #pragma unroll
        for (int j = 0; j < 8; j++)
            #pragma unroll
            for (int p = 0; p < 4; p++) C[i][j][p] = 0.0f;

    // =================== GEMM2: h1 [64 x 256] @ W1 (16 x 16k chunks) ===================
    for (int i = 0; i < 16; i++) {
        {   // MMA(i): stage i&1 (W1 chunk i), A from h1 at k = i*16
            const uint32_t bs = (uint32_t)(i & 1) * 16384u;
            uint32_t ah[2][4], al[2][4];
            #pragma unroll
            for (int m = 0; m < 2; m++) {
                int r = mw * 32 + m * 16 + qr;
                uint32_t xr = (uint32_t)(qr << 4);
                uint32_t base = (uint32_t)(r * 512);
                uint32_t o0 = ((uint32_t)(i * 32 + qc)) ^ xr;
                uint32_t o2 = ((uint32_t)(i * 32 + qc + 16)) ^ xr;
                ah[m][0] = *(const uint32_t*)(smc + H1H + base + o0);
                ah[m][1] = *(const uint32_t*)(smc + H1H + base + 4096 + o0);
                ah[m][2] = *(const uint32_t*)(smc + H1H + base + o2);
                ah[m][3] = *(const uint32_t*)(smc + H1H + base + 4096 + o2);
                al[m][0] = *(const uint32_t*)(smc + H1L + base + o0);
                al[m][1] = *(const uint32_t*)(smc + H1L + base + 4096 + o0);
                al[m][2] = *(const uint32_t*)(smc + H1L + base + o2);
                al[m][3] = *(const uint32_t*)(smc + H1L + base + 4096 + o2);
            }
            #pragma unroll
            for (int j = 0; j < 8; j++) {
                int n = nw * 64 + j * 8 + qr;
                uint32_t xn = (uint32_t)((n & 4) << 2);
                uint32_t bb = bs + (uint32_t)(n * 32);
                uint32_t o0 = ((uint32_t)qc) ^ xn;
                uint32_t o1 = ((uint32_t)(qc + 16)) ^ xn;
                uint32_t bh0 = *(const uint32_t*)(smc + bb + o0);
                uint32_t bh1 = *(const uint32_t*)(smc + bb + o1);
                uint32_t bl0 = *(const uint32_t*)(smc + bb + 8192 + o0);
                uint32_t bl1 = *(const uint32_t*)(smc + bb + 8192 + o1);
                #pragma unroll
                for (int m = 0; m < 2; m++) {
                    mma16816(C[m][j], ah[m], bh0, bh1);
                    mma16816(C[m][j], ah[m], bl0, bl1);
                    mma16816(C[m][j], al[m], bh0, bh1);
                }
            }
        }
        CP_WAIT0();
        __syncthreads();
        if (i + 2 < 16) { issueB16(sb, 24 + i + 2, tid); CP_COMMIT(); }
    }

    // ====== Epilogue 2: BN1+ReLU, dot W2, reduce, exp, segment atomics ======
    {
        const float* sS1  = (const float*)(smc + P_S1);
        const float* sSH1 = (const float*)(smc + P_SH1);
        const float* sW2  = (const float*)(smc + P_W2);
        float pl[2][2] = {{0.f, 0.f}, {0.f, 0.f}};
        #pragma unroll
        for (int m = 0; m < 2; m++) {
            #pragma unroll
            for (int j = 0; j < 8; j++) {
                int col = nw * 64 + j * 8 + (lane & 3) * 2;
                float s1a = sS1[col], s1b = sS1[col + 1];
                float h1a = sSH1[col], h1b = sSH1[col + 1];
                float w2a = sW2[col], w2b = sW2[col + 1];
                pl[m][0] = fmaf(fmaxf(fmaf(C[m][j][0], s1a, h1a), 0.f), w2a, pl[m][0]);
                pl[m][0] = fmaf(fmaxf(fmaf(C[m][j][1], s1b, h1b), 0.f), w2b, pl[m][0]);
                pl[m][1] = fmaf(fmaxf(fmaf(C[m][j][2], s1a, h1a), 0.f), w2a, pl[m][1]);
                pl[m][1] = fmaf(fmaxf(fmaf(C[m][j][3], s1b, h1b), 0.f), w2b, pl[m][1]);
            }
        }
        #pragma unroll
        for (int off = 1; off <= 2; off <<= 1)
            #pragma unroll
            for (int m = 0; m < 2; m++) {
                pl[m][0] += __shfl_xor_sync(0xffffffffu, pl[m][0], off);
                pl[m][1] += __shfl_xor_sync(0xffffffffu, pl[m][1], off);
            }
        float* part = (float*)(smc + PART);
        if ((lane & 3) == 0) {
            #pragma unroll
            for (int m = 0; m < 2; m++) {
                int r = mw * 32 + m * 16 + qr;
                part[nw * 64 + r]     = pl[m][0];
                part[nw * 64 + r + 8] = pl[m][1];
            }
        }
        __syncthreads();
        if (tid < MTILE) {
            float logit = part[tid] + part[64 + tid] + part[128 + tid] +
                          part[192 + tid] + b2[0];
            float av = expf(logit);
            out[row0 + tid] = av;
            atomicAdd(&g_norm[sidx[tid]], av);
        }
    }
}

// ======================= launch =======================
extern "C" void kernel_launch(void* const* d_in, const int* in_sizes, int n_in,
                              void* d_out, int out_size) {
    const float* x      = (const float*)d_in[0];
    const int*   bidx   = (const int*)  d_in[1];
    const float* gf     = (const float*)d_in[2];
    const float* W0     = (const float*)d_in[3];
    const float* b0     = (const float*)d_in[4];
    const float* W1     = (const float*)d_in[5];
    const float* b1     = (const float*)d_in[6];
    const float* W2     = (const float*)d_in[7];
    const float* b2     = (const float*)d_in[8];
    const float* gamma0 = (const float*)d_in[9];
    const float* beta0  = (const float*)d_in[10];
    const float* mean0  = (const float*)d_in[11];
    const float* var0   = (const float*)d_in[12];
    const float* gamma1 = (const float*)d_in[13];
    const float* beta1  = (const float*)d_in[14];
    const float* mean1  = (const float*)d_in[15];
    const float* var1   = (const float*)d_in[16];
    float* out = (float*)d_out;

    static uint16_t *pW0hi = nullptr, *pW0lo, *pW1hi, *pW1lo;
    if (!pW0hi) {
        cudaGetSymbolAddress((void**)&pW0hi, gW0hi);
        cudaGetSymbolAddress((void**)&pW0lo, gW0lo);
        cudaGetSymbolAddress((void**)&pW1hi, gW1hi);
        cudaGetSymbolAddress((void**)&pW1lo, gW1lo);
        cudaFuncSetAttribute(att_kernel, cudaFuncAttributeMaxDynamicSharedMemorySize,
                             SMEM_TOTAL);
    }

    prep_w_kernel<<<DIN, 256>>>(W0, pW0hi, pW0lo);
    prep_w_kernel<<<HID, 256>>>(W1, pW1hi, pW1lo);
    zero_norm_kernel<<<NG / 256, 256>>>();
    att_kernel<<<NCTA, NTHR, SMEM_TOTAL>>>(
        x, bidx, gf, b0, W2, b2,
        gamma0, beta0, mean0, var0,
        b1, gamma1, beta1, mean1, var1, out);
    norm_kernel<<<NN / 256, 256>>>(bidx, out);
}

// round 7
// speedup vs baseline: 6.1576x; 1.4325x over previous
#include <cuda_runtime.h>
#include <cuda_fp16.h>
#include <math.h>
#include <stdint.h>

#define NN   262144
#define NG   2048
#define DX   256
#define DG   128
#define DIN  384
#define HID  256
#define BN_EPS 1e-3f
#define MTILE 64
#define NCTA (NN / MTILE)
#define NTHR 256

// ---- smem byte map (104,704 B per CTA; 2 CTAs/SM) ----
// B stages: stage s @ s*16384, [256 n][32 k] fp16, 64B rows, XOR (n&7)<<3 ; 32KB
#define ABUF   32768    // A dbl-buf (GEMM1 only, overlays h1): buf p @ +p*8192 (hi 4K, lo 4K)
#define H1H    32768    // h1 hi [64 m][256 k] fp16, 512B rows, XOR (r&7)<<4 ; 32KB
#define H1L    65536    // h1 lo ; 32KB
#define P_S0   98304
#define P_SH0  99328
#define P_S1   100352
#define P_SH1  101376
#define P_W2   102400
#define SIDX   103424   // 256B
#define PART   103680   // 1KB float[4][64]
#define SMEM_TOTAL 104704

__device__ float g_norm[NG];
// pre-transposed, pre-swizzled fp16 weight images:
// per 32-k chunk: [n=256][k=32] fp16 = 16KB, 64B rows, XOR (n&7)<<3
__device__ __align__(16) uint16_t gW0[12 * 8192];
__device__ __align__(16) uint16_t gW1[8 * 8192];

// ======================= helpers =======================
__device__ __forceinline__ uint32_t smem_u32(const void* p) {
    uint32_t a;
    asm("{ .reg .u64 t; cvta.to.shared.u64 t, %1; cvt.u32.u64 %0, t; }"
        : "=r"(a) : "l"(p));
    return a;
}
__device__ __forceinline__ void cp16(uint32_t dst, const void* src) {
    asm volatile("cp.async.cg.shared.global [%0], [%1], 16;"
                 :: "r"(dst), "l"(__cvta_generic_to_global(src)) : "memory");
}
#define CP_COMMIT() asm volatile("cp.async.commit_group;" ::: "memory")
#define CP_WAIT0()  asm volatile("cp.async.wait_group 0;" ::: "memory")
#define CP_WAIT1()  asm volatile("cp.async.wait_group 1;" ::: "memory")

__device__ __forceinline__ void hsplit(float f, uint16_t& h, uint16_t& l) {
    __half hb = __float2half(f);
    __half lb = __float2half(f - __half2float(hb));
    h = __half_as_ushort(hb);
    l = __half_as_ushort(lb);
}
__device__ __forceinline__ void mma16816h(float* c, const uint32_t* a,
                                          uint32_t b0, uint32_t b1) {
    asm volatile(
        "mma.sync.aligned.m16n8k16.row.col.f32.f16.f16.f32 "
        "{%0,%1,%2,%3}, {%4,%5,%6,%7}, {%8,%9}, {%0,%1,%2,%3};"
        : "+f"(c[0]), "+f"(c[1]), "+f"(c[2]), "+f"(c[3])
        : "r"(a[0]), "r"(a[1]), "r"(a[2]), "r"(a[3]), "r"(b0), "r"(b1));
}

// ======================= small kernels =======================
__global__ void zero_norm_kernel() {
    g_norm[blockIdx.x * 256 + threadIdx.x] = 0.0f;
}

// W:[K,256] row-major -> per-32k-chunk fp16 images [256][32], 64B rows, XOR (n&7)<<3
__global__ void prep_w_kernel(const float* __restrict__ W,
                              uint16_t* __restrict__ dst) {
    int idx = blockIdx.x * 256 + threadIdx.x;
    int k = idx >> 8, n = idx & 255;
    float v = W[(size_t)k * 256 + n];
    uint32_t off = (uint32_t)(k >> 5) * 16384u + (uint32_t)n * 64u +
                   (((uint32_t)(k & 31) * 2u) ^ ((uint32_t)(n & 7) << 3));
    dst[off >> 1] = __half_as_ushort(__float2half(v));
}

__global__ void norm_kernel(const int* __restrict__ bidx, float* __restrict__ out) {
    int i = blockIdx.x * 256 + threadIdx.x;
    out[i] = out[i] / g_norm[bidx[i]];
}

// ======================= device sub-steps =======================
// cp.async one 16KB fp16 weight chunk into stage g&1
__device__ __forceinline__ void issueB(uint32_t sb, int g, int tid) {
    const uint16_t* src = (g < 12) ? (gW0 + g * 8192) : (gW1 + (g - 12) * 8192);
    uint32_t d = sb + (uint32_t)(g & 1) * 16384u;
    #pragma unroll
    for (int i = tid; i < 1024; i += NTHR)
        cp16(d + i * 16, (const char*)src + i * 16);
}

// register-pipelined A chunk load: 64 rows x 32 k fp32 -> 2 float4 per thread
__device__ __forceinline__ void ldgA(int c, const float* x, const float* gf,
                                     const int* sidx, int row0, int tid,
                                     float4& f0, float4& f1) {
    int r = tid >> 2, q = tid & 3;           // row 0..63, quarter 0..3
    const float* src = (c < 8)
        ? (x + (size_t)(row0 + r) * DX + c * 32 + q * 8)
        : (gf + (size_t)sidx[r] * DG + (c - 8) * 32 + q * 8);
    f0 = *(const float4*)src;
    f1 = *((const float4*)src + 1);
}

// fp16-split 8 floats into A image buf p (hi @ +0, lo @ +4096)
__device__ __forceinline__ void stsA(char* smc, int p, float4 f0, float4 f1, int tid) {
    int r = tid >> 2, q = tid & 3;
    uint16_t h[8], l[8];
    hsplit(f0.x, h[0], l[0]); hsplit(f0.y, h[1], l[1]);
    hsplit(f0.z, h[2], l[2]); hsplit(f0.w, h[3], l[3]);
    hsplit(f1.x, h[4], l[4]); hsplit(f1.y, h[5], l[5]);
    hsplit(f1.z, h[6], l[6]); hsplit(f1.w, h[7], l[7]);
    uint32_t xr = (uint32_t)((r & 7) << 3);
    uint32_t base = ABUF + (uint32_t)p * 8192u + (uint32_t)(r * 64);
    uint32_t o0 = ((uint32_t)(q * 16)) ^ xr;
    uint32_t o1 = ((uint32_t)(q * 16 + 8)) ^ xr;
    *(uint2*)(smc + base + o0) = make_uint2(
        (uint32_t)h[0] | ((uint32_t)h[1] << 16), (uint32_t)h[2] | ((uint32_t)h[3] << 16));
    *(uint2*)(smc + base + o1) = make_uint2(
        (uint32_t)h[4] | ((uint32_t)h[5] << 16), (uint32_t)h[6] | ((uint32_t)h[7] << 16));
    *(uint2*)(smc + base + 4096 + o0) = make_uint2(
        (uint32_t)l[0] | ((uint32_t)l[1] << 16), (uint32_t)l[2] | ((uint32_t)l[3] << 16));
    *(uint2*)(smc + base + 4096 + o1) = make_uint2(
        (uint32_t)l[4] | ((uint32_t)l[5] << 16), (uint32_t)l[6] | ((uint32_t)l[7] << 16));
}

// ======================= main fused kernel =======================
__global__ __launch_bounds__(NTHR, 2) void att_kernel(
    const float* __restrict__ x, const int* __restrict__ bidx,
    const float* __restrict__ gf,
    const float* __restrict__ b0,
    const float* __restrict__ W2, const float* __restrict__ b2,
    const float* __restrict__ gamma0, const float* __restrict__ beta0,
    const float* __restrict__ mean0, const float* __restrict__ var0,
    const float* __restrict__ b1,
    const float* __restrict__ gamma1, const float* __restrict__ beta1,
    const float* __restrict__ mean1, const float* __restrict__ var1,
    float* __restrict__ out)
{
    extern __shared__ char smc[];
    const uint32_t sb = smem_u32(smc);
    const int tid = threadIdx.x;
    const int wid = tid >> 5;
    const int lane = tid & 31;
    const int row0 = blockIdx.x * MTILE;
    const int mw = wid >> 2;          // 0..1  M groups of 32
    const int nw = wid & 3;           // 0..3  N groups of 64
    const int qr = lane >> 2;         // 0..7
    const int qc = (lane & 3) * 4;    // k-pair byte offset

    int* sidx = (int*)(smc + SIDX);
    if (tid < MTILE) sidx[tid] = bidx[row0 + tid];
    {   // fold BN params (256 threads = 256 cols)
        int cc = tid;
        float s0v = gamma0[cc] * rsqrtf(var0[cc] + BN_EPS);
        ((float*)(smc + P_S0))[cc]  = s0v;
        ((float*)(smc + P_SH0))[cc] = fmaf(b0[cc] - mean0[cc], s0v, beta0[cc]);
        float s1v = gamma1[cc] * rsqrtf(var1[cc] + BN_EPS);
        ((float*)(smc + P_S1))[cc]  = s1v;
        ((float*)(smc + P_SH1))[cc] = fmaf(b1[cc] - mean1[cc], s1v, beta1[cc]);
        ((float*)(smc + P_W2))[cc]  = W2[cc];
    }

    // prologue: stage W0 c0+c1, convert A(0)
    issueB(sb, 0, tid); CP_COMMIT();
    issueB(sb, 1, tid); CP_COMMIT();
    {
        float4 f0, f1;
        ldgA(0, x, gf, sidx, row0, tid, f0, f1);   // c0 < 8: no sidx use
        stsA(smc, 0, f0, f1, tid);
    }
    CP_WAIT1();          // c0 landed
    __syncthreads();     // A(0), params, sidx visible

    float C[2][8][4];
    #pragma unroll
    for (int i = 0; i < 2; i++)
        #pragma unroll
        for (int j = 0; j < 8; j++)
            #pragma unroll
            for (int p = 0; p < 4; p++) C[i][j][p] = 0.0f;

    // =================== GEMM1: [64 x 384] @ W0 (12 x 32k chunks) ===================
    for (int i = 0; i < 12; i++) {
        float4 fA0, fA1;
        if (i + 1 < 12) ldgA(i + 1, x, gf, sidx, row0, tid, fA0, fA1);

        {   // MMA(i): stage i&1, abuf i&1
            const uint32_t bs = (uint32_t)(i & 1) * 16384u;
            const uint32_t ab = ABUF + (uint32_t)(i & 1) * 8192u;
            #pragma unroll
            for (int ks = 0; ks < 2; ks++) {
                uint32_t ah[2][4], al[2][4];
                #pragma unroll
                for (int m = 0; m < 2; m++) {
                    int r = mw * 32 + m * 16 + qr;
                    uint32_t xr = (uint32_t)(qr << 3);
                    uint32_t base = ab + (uint32_t)(r * 64);
                    uint32_t o0 = ((uint32_t)(ks * 32 + qc)) ^ xr;
                    uint32_t o2 = ((uint32_t)(ks * 32 + qc + 16)) ^ xr;
                    ah[m][0] = *(const uint32_t*)(smc + base + o0);
                    ah[m][1] = *(const uint32_t*)(smc + base + 512 + o0);
                    ah[m][2] = *(const uint32_t*)(smc + base + o2);
                    ah[m][3] = *(const uint32_t*)(smc + base + 512 + o2);
                    al[m][0] = *(const uint32_t*)(smc + base + 4096 + o0);
                    al[m][1] = *(const uint32_t*)(smc + base + 4608 + o0);
                    al[m][2] = *(const uint32_t*)(smc + base + 4096 + o2);
                    al[m][3] = *(const uint32_t*)(smc + base + 4608 + o2);
                }
                #pragma unroll
                for (int j = 0; j < 8; j++) {
                    int n = nw * 64 + j * 8 + qr;
                    uint32_t xn = (uint32_t)(qr << 3);
                    uint32_t bb = bs + (uint32_t)(n * 64);
                    uint32_t b0v = *(const uint32_t*)(smc + bb + (((uint32_t)(ks * 32 + qc)) ^ xn));
                    uint32_t b1v = *(const uint32_t*)(smc + bb + (((uint32_t)(ks * 32 + qc + 16)) ^ xn));
                    #pragma unroll
                    for (int m = 0; m < 2; m++) {
                        mma16816h(C[m][j], ah[m], b0v, b1v);
                        mma16816h(C[m][j], al[m], b0v, b1v);
                    }
                }
            }
        }

        if (i + 1 < 12) stsA(smc, (i + 1) & 1, fA0, fA1, tid);
        CP_WAIT0();          // B chunk i+1 landed
        __syncthreads();     // A(i+1) visible; stage i&1 free
        issueB(sb, i + 2, tid);     // tail issues W1 c0/c1 (g=12,13)
        CP_COMMIT();
    }

    // ====== Epilogue 1: BN0+ReLU, fp16 split, write h1 (overlaps W1 c1 copy) ======
    {
        const float* sS0  = (const float*)(smc + P_S0);
        const float* sSH0 = (const float*)(smc + P_SH0);
        #pragma unroll
        for (int m = 0; m < 2; m++) {
            int r = mw * 32 + m * 16 + qr;
            uint32_t xr0 = (uint32_t)(qr << 4);
            uint32_t rb0 = (uint32_t)(r * 512);
            uint32_t rb1 = (uint32_t)((r + 8) * 512);
            #pragma unroll
            for (int j = 0; j < 8; j++) {
                int col = nw * 64 + j * 8 + (lane & 3) * 2;
                float s0a = sS0[col], s0b = sS0[col + 1];
                float h0a = sSH0[col], h0b = sSH0[col + 1];
                float v00 = fmaxf(fmaf(C[m][j][0], s0a, h0a), 0.f);
                float v01 = fmaxf(fmaf(C[m][j][1], s0b, h0b), 0.f);
                float v10 = fmaxf(fmaf(C[m][j][2], s0a, h0a), 0.f);
                float v11 = fmaxf(fmaf(C[m][j][3], s0b, h0b), 0.f);
                uint16_t h00, l00, h01, l01, h10, l10, h11, l11;
                hsplit(v00, h00, l00); hsplit(v01, h01, l01);
                hsplit(v10, h10, l10); hsplit(v11, h11, l11);
                uint32_t ko = ((uint32_t)(col * 2)) ^ xr0;
                *(uint32_t*)(smc + H1H + rb0 + ko) = (uint32_t)h00 | ((uint32_t)h01 << 16);
                *(uint32_t*)(smc + H1L + rb0 + ko) = (uint32_t)l00 | ((uint32_t)l01 << 16);
                *(uint32_t*)(smc + H1H + rb1 + ko) = (uint32_t)h10 | ((uint32_t)h11 << 16);
                *(uint32_t*)(smc + H1L + rb1 + ko) = (uint32_t)l10 | ((uint32_t)l11 << 16);
            }
        }
    }
    CP_WAIT0();          // W1 c0+c1 landed
    __syncthreads();     // h1 visible

    #pragma unroll
    for (int i = 0; i < 2; i++)
        #pragma unroll
        for (int j = 0; j < 8; j++)
            #pragma unroll
            for (int p = 0; p < 4; p++) C[i][j][p] = 0.0f;

    // =================== GEMM2: h1 [64 x 256] @ W1 (8 x 32k chunks) ===================
    for (int i = 0; i < 8; i++) {
        {   // MMA(i): stage i&1 (W1 chunk i), A from h1 at k = i*32
            const uint32_t bs = (uint32_t)(i & 1) * 16384u;
            #pragma unroll
            for (int ks = 0; ks < 2; ks++) {
                uint32_t ah[2][4], al[2][4];
                #pragma unroll
                for (int m = 0; m < 2; m++) {
                    int r = mw * 32 + m * 16 + qr;
                    uint32_t xr = (uint32_t)(qr << 4);
                    uint32_t base = (uint32_t)(r * 512);
                    uint32_t o0 = ((uint32_t)((i * 2 + ks) * 32 + qc)) ^ xr;
                    uint32_t o2 = ((uint32_t)((i * 2 + ks) * 32 + qc + 16)) ^ xr;
                    ah[m][0] = *(const uint32_t*)(smc + H1H + base + o0);
                    ah[m][1] = *(const uint32_t*)(smc + H1H + base + 4096 + o0);
                    ah[m][2] = *(const uint32_t*)(smc + H1H + base + o2);
                    ah[m][3] = *(const uint32_t*)(smc + H1H + base + 4096 + o2);
                    al[m][0] = *(const uint32_t*)(smc + H1L + base + o0);
                    al[m][1] = *(const uint32_t*)(smc + H1L + base + 4096 + o0);
                    al[m][2] = *(const uint32_t*)(smc + H1L + base + o2);
                    al[m][3] = *(const uint32_t*)(smc + H1L + base + 4096 + o2);
                }
                #pragma unroll
                for (int j = 0; j < 8; j++) {
                    int n = nw * 64 + j * 8 + qr;
                    uint32_t xn = (uint32_t)(qr << 3);
                    uint32_t bb = bs + (uint32_t)(n * 64);
                    uint32_t b0v = *(const uint32_t*)(smc + bb + (((uint32_t)(ks * 32 + qc)) ^ xn));
                    uint32_t b1v = *(const uint32_t*)(smc + bb + (((uint32_t)(ks * 32 + qc + 16)) ^ xn));
                    #pragma unroll
                    for (int m = 0; m < 2; m++) {
                        mma16816h(C[m][j], ah[m], b0v, b1v);
                        mma16816h(C[m][j], al[m], b0v, b1v);
                    }
                }
            }
        }
        CP_WAIT0();
        __syncthreads();
        if (i + 2 < 8) { issueB(sb, 12 + i + 2, tid); CP_COMMIT(); }
    }

    // ====== Epilogue 2: BN1+ReLU, dot W2, reduce, exp, segment atomics ======
    {
        const float* sS1  = (const float*)(smc + P_S1);
        const float* sSH1 = (const float*)(smc + P_SH1);
        const float* sW2  = (const float*)(smc + P_W2);
        float pl[2][2] = {{0.f, 0.f}, {0.f, 0.f}};
        #pragma unroll
        for (int m = 0; m < 2; m++) {
            #pragma unroll
            for (int j = 0; j < 8; j++) {
                int col = nw * 64 + j * 8 + (lane & 3) * 2;
                float s1a = sS1[col], s1b = sS1[col + 1];
                float h1a = sSH1[col], h1b = sSH1[col + 1];
                float w2a = sW2[col], w2b = sW2[col + 1];
                pl[m][0] = fmaf(fmaxf(fmaf(C[m][j][0], s1a, h1a), 0.f), w2a, pl[m][0]);
                pl[m][0] = fmaf(fmaxf(fmaf(C[m][j][1], s1b, h1b), 0.f), w2b, pl[m][0]);
                pl[m][1] = fmaf(fmaxf(fmaf(C[m][j][2], s1a, h1a), 0.f), w2a, pl[m][1]);
                pl[m][1] = fmaf(fmaxf(fmaf(C[m][j][3], s1b, h1b), 0.f), w2b, pl[m][1]);
            }
        }
        #pragma unroll
        for (int off = 1; off <= 2; off <<= 1)
            #pragma unroll
            for (int m = 0; m < 2; m++) {
                pl[m][0] += __shfl_xor_sync(0xffffffffu, pl[m][0], off);
                pl[m][1] += __shfl_xor_sync(0xffffffffu, pl[m][1], off);
            }
        float* part = (float*)(smc + PART);
        if ((lane & 3) == 0) {
            #pragma unroll
            for (int m = 0; m < 2; m++) {
                int r = mw * 32 + m * 16 + qr;
                part[nw * 64 + r]     = pl[m][0];
                part[nw * 64 + r + 8] = pl[m][1];
            }
        }
        __syncthreads();
        if (tid < MTILE) {
            float logit = part[tid] + part[64 + tid] + part[128 + tid] +
                          part[192 + tid] + b2[0];
            float av = expf(logit);
            out[row0 + tid] = av;
            atomicAdd(&g_norm[sidx[tid]], av);
        }
    }
}

// ======================= launch =======================
extern "C" void kernel_launch(void* const* d_in, const int* in_sizes, int n_in,
                              void* d_out, int out_size) {
    const float* x      = (const float*)d_in[0];
    const int*   bidx   = (const int*)  d_in[1];
    const float* gf     = (const float*)d_in[2];
    const float* W0     = (const float*)d_in[3];
    const float* b0     = (const float*)d_in[4];
    const float* W1     = (const float*)d_in[5];
    const float* b1     = (const float*)d_in[6];
    const float* W2     = (const float*)d_in[7];
    const float* b2     = (const float*)d_in[8];
    const float* gamma0 = (const float*)d_in[9];
    const float* beta0  = (const float*)d_in[10];
    const float* mean0  = (const float*)d_in[11];
    const float* var0   = (const float*)d_in[12];
    const float* gamma1 = (const float*)d_in[13];
    const float* beta1  = (const float*)d_in[14];
    const float* mean1  = (const float*)d_in[15];
    const float* var1   = (const float*)d_in[16];
    float* out = (float*)d_out;

    static uint16_t *pW0 = nullptr, *pW1;
    if (!pW0) {
        cudaGetSymbolAddress((void**)&pW0, gW0);
        cudaGetSymbolAddress((void**)&pW1, gW1);
        cudaFuncSetAttribute(att_kernel, cudaFuncAttributeMaxDynamicSharedMemorySize,
                             SMEM_TOTAL);
    }

    prep_w_kernel<<<DIN, 256>>>(W0, pW0);
    prep_w_kernel<<<HID, 256>>>(W1, pW1);
    zero_norm_kernel<<<NG / 256, 256>>>();
    att_kernel<<<NCTA, NTHR, SMEM_TOTAL>>>(
        x, bidx, gf, b0, W2, b2,
        gamma0, beta0, mean0, var0,
        b1, gamma1, beta1, mean1, var1, out);
    norm_kernel<<<NN / 256, 256>>>(bidx, out);
}

// round 8
// speedup vs baseline: 9.6281x; 1.5636x over previous
#include <cuda_runtime.h>
#include <cuda_fp16.h>
#include <math.h>
#include <stdint.h>

#define NN   262144
#define NG   2048
#define DX   256
#define DG   128
#define DIN  384
#define HID  256
#define BN_EPS 1e-3f
#define MTILE 64
#define NCTA (NN / MTILE)
#define NTHR 256

// ---- smem byte map (71,936 B per CTA; 2 CTAs/SM) ----
// B stages: stage s @ s*16384, [256 n][32 k] fp16, 64B rows, XOR (n&7)<<3 ; 32KB
#define ABUF   32768    // A dbl-buf (GEMM1 only, overlays h1): buf p @ +p*4096 ; 8KB
#define H1     32768    // h1 [64 m][256 k] fp16, 512B rows, XOR (r&7)<<4 ; 32KB
#define P_S0   65536
#define P_SH0  66560
#define P_S1   67584
#define P_SH1  68608
#define P_W2   69632
#define SIDX   70656    // 256B
#define PART   70912    // 1KB float[4][64]
#define SMEM_TOTAL 71936

__device__ float g_norm[NG];
// pre-transposed, pre-swizzled fp16 weight images:
// per 32-k chunk: [n=256][k=32] fp16 = 16KB, 64B rows, XOR (n&7)<<3
__device__ __align__(16) uint16_t gW0[12 * 8192];
__device__ __align__(16) uint16_t gW1[8 * 8192];

// ======================= helpers =======================
__device__ __forceinline__ uint32_t smem_u32(const void* p) {
    uint32_t a;
    asm("{ .reg .u64 t; cvta.to.shared.u64 t, %1; cvt.u32.u64 %0, t; }"
        : "=r"(a) : "l"(p));
    return a;
}
__device__ __forceinline__ void cp16(uint32_t dst, const void* src) {
    asm volatile("cp.async.cg.shared.global [%0], [%1], 16;"
                 :: "r"(dst), "l"(__cvta_generic_to_global(src)) : "memory");
}
#define CP_COMMIT() asm volatile("cp.async.commit_group;" ::: "memory")
#define CP_WAIT0()  asm volatile("cp.async.wait_group 0;" ::: "memory")
#define CP_WAIT1()  asm volatile("cp.async.wait_group 1;" ::: "memory")

__device__ __forceinline__ void mma16816h(float* c, const uint32_t* a,
                                          uint32_t b0, uint32_t b1) {
    asm volatile(
        "mma.sync.aligned.m16n8k16.row.col.f32.f16.f16.f32 "
        "{%0,%1,%2,%3}, {%4,%5,%6,%7}, {%8,%9}, {%0,%1,%2,%3};"
        : "+f"(c[0]), "+f"(c[1]), "+f"(c[2]), "+f"(c[3])
        : "r"(a[0]), "r"(a[1]), "r"(a[2]), "r"(a[3]), "r"(b0), "r"(b1));
}
__device__ __forceinline__ uint32_t pack2h(float a, float b) {
    __half2 h = __floats2half2_rn(a, b);
    return *(uint32_t*)&h;
}

// ======================= small kernels =======================
__global__ void zero_norm_kernel() {
    g_norm[blockIdx.x * 256 + threadIdx.x] = 0.0f;
}

// W:[K,256] row-major -> per-32k-chunk fp16 images [256][32], 64B rows, XOR (n&7)<<3
__global__ void prep_w_kernel(const float* __restrict__ W,
                              uint16_t* __restrict__ dst) {
    int idx = blockIdx.x * 256 + threadIdx.x;
    int k = idx >> 8, n = idx & 255;
    float v = W[(size_t)k * 256 + n];
    uint32_t off = (uint32_t)(k >> 5) * 16384u + (uint32_t)n * 64u +
                   (((uint32_t)(k & 31) * 2u) ^ ((uint32_t)(n & 7) << 3));
    dst[off >> 1] = __half_as_ushort(__float2half(v));
}

__global__ void norm_kernel(const int* __restrict__ bidx, float* __restrict__ out) {
    int i = blockIdx.x * 256 + threadIdx.x;
    out[i] = out[i] / g_norm[bidx[i]];
}

// ======================= device sub-steps =======================
// cp.async one 16KB fp16 weight chunk into stage g&1
__device__ __forceinline__ void issueB(uint32_t sb, int g, int tid) {
    const uint16_t* src = (g < 12) ? (gW0 + g * 8192) : (gW1 + (g - 12) * 8192);
    uint32_t d = sb + (uint32_t)(g & 1) * 16384u;
    #pragma unroll
    for (int i = tid; i < 1024; i += NTHR)
        cp16(d + i * 16, (const char*)src + i * 16);
}

// register-pipelined A chunk load: 64 rows x 32 k fp32 -> 2 float4 per thread
__device__ __forceinline__ void ldgA(int c, const float* x, const float* gf,
                                     const int* sidx, int row0, int tid,
                                     float4& f0, float4& f1) {
    int r = tid >> 2, q = tid & 3;           // row 0..63, quarter 0..3
    const float* src = (c < 8)
        ? (x + (size_t)(row0 + r) * DX + c * 32 + q * 8)
        : (gf + (size_t)sidx[r] * DG + (c - 8) * 32 + q * 8);
    f0 = *(const float4*)src;
    f1 = *((const float4*)src + 1);
}

// fp16-convert 8 floats into A image buf p
__device__ __forceinline__ void stsA(char* smc, int p, float4 f0, float4 f1, int tid) {
    int r = tid >> 2, q = tid & 3;
    uint32_t xr = (uint32_t)((r & 7) << 3);
    uint32_t base = ABUF + (uint32_t)p * 4096u + (uint32_t)(r * 64);
    uint32_t o0 = ((uint32_t)(q * 16)) ^ xr;
    uint32_t o1 = ((uint32_t)(q * 16 + 8)) ^ xr;
    *(uint2*)(smc + base + o0) = make_uint2(pack2h(f0.x, f0.y), pack2h(f0.z, f0.w));
    *(uint2*)(smc + base + o1) = make_uint2(pack2h(f1.x, f1.y), pack2h(f1.z, f1.w));
}

// ======================= main fused kernel =======================
__global__ __launch_bounds__(NTHR, 2) void att_kernel(
    const float* __restrict__ x, const int* __restrict__ bidx,
    const float* __restrict__ gf,
    const float* __restrict__ b0,
    const float* __restrict__ W2, const float* __restrict__ b2,
    const float* __restrict__ gamma0, const float* __restrict__ beta0,
    const float* __restrict__ mean0, const float* __restrict__ var0,
    const float* __restrict__ b1,
    const float* __restrict__ gamma1, const float* __restrict__ beta1,
    const float* __restrict__ mean1, const float* __restrict__ var1,
    float* __restrict__ out)
{
    extern __shared__ char smc[];
    const uint32_t sb = smem_u32(smc);
    const int tid = threadIdx.x;
    const int wid = tid >> 5;
    const int lane = tid & 31;
    const int row0 = blockIdx.x * MTILE;
    const int mw = wid >> 2;          // 0..1  M groups of 32
    const int nw = wid & 3;           // 0..3  N groups of 64
    const int qr = lane >> 2;         // 0..7
    const int qc = (lane & 3) * 4;    // k-pair byte offset

    int* sidx = (int*)(smc + SIDX);
    if (tid < MTILE) sidx[tid] = bidx[row0 + tid];
    {   // fold BN params (256 threads = 256 cols)
        int cc = tid;
        float s0v = gamma0[cc] * rsqrtf(var0[cc] + BN_EPS);
        ((float*)(smc + P_S0))[cc]  = s0v;
        ((float*)(smc + P_SH0))[cc] = fmaf(b0[cc] - mean0[cc], s0v, beta0[cc]);
        float s1v = gamma1[cc] * rsqrtf(var1[cc] + BN_EPS);
        ((float*)(smc + P_S1))[cc]  = s1v;
        ((float*)(smc + P_SH1))[cc] = fmaf(b1[cc] - mean1[cc], s1v, beta1[cc]);
        ((float*)(smc + P_W2))[cc]  = W2[cc];
    }

    // prologue: stage W0 c0+c1, convert A(0)
    issueB(sb, 0, tid); CP_COMMIT();
    issueB(sb, 1, tid); CP_COMMIT();
    {
        float4 f0, f1;
        ldgA(0, x, gf, sidx, row0, tid, f0, f1);   // c0 < 8: no sidx use
        stsA(smc, 0, f0, f1, tid);
    }
    CP_WAIT1();          // c0 landed
    __syncthreads();     // A(0), params, sidx visible

    float C[2][8][4];
    #pragma unroll
    for (int i = 0; i < 2; i++)
        #pragma unroll
        for (int j = 0; j < 8; j++)
            #pragma unroll
            for (int p = 0; p < 4; p++) C[i][j][p] = 0.0f;

    // =================== GEMM1: [64 x 384] @ W0 (12 x 32k chunks) ===================
    for (int i = 0; i < 12; i++) {
        float4 fA0, fA1;
        if (i + 1 < 12) ldgA(i + 1, x, gf, sidx, row0, tid, fA0, fA1);

        {   // MMA(i): stage i&1, abuf i&1
            const uint32_t bs = (uint32_t)(i & 1) * 16384u;
            const uint32_t ab = ABUF + (uint32_t)(i & 1) * 4096u;
            #pragma unroll
            for (int ks = 0; ks < 2; ks++) {
                uint32_t ah[2][4];
                #pragma unroll
                for (int m = 0; m < 2; m++) {
                    int r = mw * 32 + m * 16 + qr;
                    uint32_t xr = (uint32_t)(qr << 3);
                    uint32_t base = ab + (uint32_t)(r * 64);
                    uint32_t o0 = ((uint32_t)(ks * 32 + qc)) ^ xr;
                    uint32_t o2 = ((uint32_t)(ks * 32 + qc + 16)) ^ xr;
                    ah[m][0] = *(const uint32_t*)(smc + base + o0);
                    ah[m][1] = *(const uint32_t*)(smc + base + 512 + o0);
                    ah[m][2] = *(const uint32_t*)(smc + base + o2);
                    ah[m][3] = *(const uint32_t*)(smc + base + 512 + o2);
                }
                #pragma unroll
                for (int j = 0; j < 8; j++) {
                    int n = nw * 64 + j * 8 + qr;
                    uint32_t xn = (uint32_t)(qr << 3);
                    uint32_t bb = bs + (uint32_t)(n * 64);
                    uint32_t b0v = *(const uint32_t*)(smc + bb + (((uint32_t)(ks * 32 + qc)) ^ xn));
                    uint32_t b1v = *(const uint32_t*)(smc + bb + (((uint32_t)(ks * 32 + qc + 16)) ^ xn));
                    #pragma unroll
                    for (int m = 0; m < 2; m++)
                        mma16816h(C[m][j], ah[m], b0v, b1v);
                }
            }
        }

        if (i + 1 < 12) stsA(smc, (i + 1) & 1, fA0, fA1, tid);
        CP_WAIT0();          // B chunk i+1 landed
        __syncthreads();     // A(i+1) visible; stage i&1 free
        issueB(sb, i + 2, tid);     // tail issues W1 c0/c1 (g=12,13)
        CP_COMMIT();
    }

    // ====== Epilogue 1: BN0+ReLU, fp16 convert, write h1 (overlaps W1 copies) ======
    {
        const float* sS0  = (const float*)(smc + P_S0);
        const float* sSH0 = (const float*)(smc + P_SH0);
        #pragma unroll
        for (int m = 0; m < 2; m++) {
            int r = mw * 32 + m * 16 + qr;
            uint32_t xr0 = (uint32_t)(qr << 4);
            uint32_t rb0 = (uint32_t)(r * 512);
            uint32_t rb1 = (uint32_t)((r + 8) * 512);
            #pragma unroll
            for (int j = 0; j < 8; j++) {
                int col = nw * 64 + j * 8 + (lane & 3) * 2;
                float s0a = sS0[col], s0b = sS0[col + 1];
                float h0a = sSH0[col], h0b = sSH0[col + 1];
                float v00 = fmaxf(fmaf(C[m][j][0], s0a, h0a), 0.f);
                float v01 = fmaxf(fmaf(C[m][j][1], s0b, h0b), 0.f);
                float v10 = fmaxf(fmaf(C[m][j][2], s0a, h0a), 0.f);
                float v11 = fmaxf(fmaf(C[m][j][3], s0b, h0b), 0.f);
                uint32_t ko = ((uint32_t)(col * 2)) ^ xr0;
                *(uint32_t*)(smc + H1 + rb0 + ko) = pack2h(v00, v01);
                *(uint32_t*)(smc + H1 + rb1 + ko) = pack2h(v10, v11);
            }
        }
    }
    CP_WAIT0();          // W1 c0+c1 landed
    __syncthreads();     // h1 visible

    #pragma unroll
    for (int i = 0; i < 2; i++)
        #pragma unroll
        for (int j = 0; j < 8; j++)
            #pragma unroll
            for (int p = 0; p < 4; p++) C[i][j][p] = 0.0f;

    // =================== GEMM2: h1 [64 x 256] @ W1 (8 x 32k chunks) ===================
    for (int i = 0; i < 8; i++) {
        {   // MMA(i): stage i&1 (W1 chunk i), A from h1 at k = i*32
            const uint32_t bs = (uint32_t)(i & 1) * 16384u;
            #pragma unroll
            for (int ks = 0; ks < 2; ks++) {
                uint32_t ah[2][4];
                #pragma unroll
                for (int m = 0; m < 2; m++) {
                    int r = mw * 32 + m * 16 + qr;
                    uint32_t xr = (uint32_t)(qr << 4);
                    uint32_t base = (uint32_t)(r * 512);
                    uint32_t o0 = ((uint32_t)((i * 2 + ks) * 32 + qc)) ^ xr;
                    uint32_t o2 = ((uint32_t)((i * 2 + ks) * 32 + qc + 16)) ^ xr;
                    ah[m][0] = *(const uint32_t*)(smc + H1 + base + o0);
                    ah[m][1] = *(const uint32_t*)(smc + H1 + base + 4096 + o0);
                    ah[m][2] = *(const uint32_t*)(smc + H1 + base + o2);
                    ah[m][3] = *(const uint32_t*)(smc + H1 + base + 4096 + o2);
                }
                #pragma unroll
                for (int j = 0; j < 8; j++) {
                    int n = nw * 64 + j * 8 + qr;
                    uint32_t xn = (uint32_t)(qr << 3);
                    uint32_t bb = bs + (uint32_t)(n * 64);
                    uint32_t b0v = *(const uint32_t*)(smc + bb + (((uint32_t)(ks * 32 + qc)) ^ xn));
                    uint32_t b1v = *(const uint32_t*)(smc + bb + (((uint32_t)(ks * 32 + qc + 16)) ^ xn));
                    #pragma unroll
                    for (int m = 0; m < 2; m++)
                        mma16816h(C[m][j], ah[m], b0v, b1v);
                }
            }
        }
        CP_WAIT0();
        __syncthreads();
        if (i + 2 < 8) { issueB(sb, 12 + i + 2, tid); CP_COMMIT(); }
    }

    // ====== Epilogue 2: BN1+ReLU, dot W2, reduce, exp, segment atomics ======
    {
        const float* sS1  = (const float*)(smc + P_S1);
        const float* sSH1 = (const float*)(smc + P_SH1);
        const float* sW2  = (const float*)(smc + P_W2);
        float pl[2][2] = {{0.f, 0.f}, {0.f, 0.f}};
        #pragma unroll
        for (int m = 0; m < 2; m++) {
            #pragma unroll
            for (int j = 0; j < 8; j++) {
                int col = nw * 64 + j * 8 + (lane & 3) * 2;
                float s1a = sS1[col], s1b = sS1[col + 1];
                float h1a = sSH1[col], h1b = sSH1[col + 1];
                float w2a = sW2[col], w2b = sW2[col + 1];
                pl[m][0] = fmaf(fmaxf(fmaf(C[m][j][0], s1a, h1a), 0.f), w2a, pl[m][0]);
                pl[m][0] = fmaf(fmaxf(fmaf(C[m][j][1], s1b, h1b), 0.f), w2b, pl[m][0]);
                pl[m][1] = fmaf(fmaxf(fmaf(C[m][j][2], s1a, h1a), 0.f), w2a, pl[m][1]);
                pl[m][1] = fmaf(fmaxf(fmaf(C[m][j][3], s1b, h1b), 0.f), w2b, pl[m][1]);
            }
        }
        #pragma unroll
        for (int off = 1; off <= 2; off <<= 1)
            #pragma unroll
            for (int m = 0; m < 2; m++) {
                pl[m][0] += __shfl_xor_sync(0xffffffffu, pl[m][0], off);
                pl[m][1] += __shfl_xor_sync(0xffffffffu, pl[m][1], off);
            }
        float* part = (float*)(smc + PART);
        if ((lane & 3) == 0) {
            #pragma unroll
            for (int m = 0; m < 2; m++) {
                int r = mw * 32 + m * 16 + qr;
                part[nw * 64 + r]     = pl[m][0];
                part[nw * 64 + r + 8] = pl[m][1];
            }
        }
        __syncthreads();
        if (tid < MTILE) {
            float logit = part[tid] + part[64 + tid] + part[128 + tid] +
                          part[192 + tid] + b2[0];
            float av = expf(logit);
            out[row0 + tid] = av;
            atomicAdd(&g_norm[sidx[tid]], av);
        }
    }
}

// ======================= launch =======================
extern "C" void kernel_launch(void* const* d_in, const int* in_sizes, int n_in,
                              void* d_out, int out_size) {
    const float* x      = (const float*)d_in[0];
    const int*   bidx   = (const int*)  d_in[1];
    const float* gf     = (const float*)d_in[2];
    const float* W0     = (const float*)d_in[3];
    const float* b0     = (const float*)d_in[4];
    const float* W1     = (const float*)d_in[5];
    const float* b1     = (const float*)d_in[6];
    const float* W2     = (const float*)d_in[7];
    const float* b2     = (const float*)d_in[8];
    const float* gamma0 = (const float*)d_in[9];
    const float* beta0  = (const float*)d_in[10];
    const float* mean0  = (const float*)d_in[11];
    const float* var0   = (const float*)d_in[12];
    const float* gamma1 = (const float*)d_in[13];
    const float* beta1  = (const float*)d_in[14];
    const float* mean1  = (const float*)d_in[15];
    const float* var1   = (const float*)d_in[16];
    float* out = (float*)d_out;

    static uint16_t *pW0 = nullptr, *pW1;
    if (!pW0) {
        cudaGetSymbolAddress((void**)&pW0, gW0);
        cudaGetSymbolAddress((void**)&pW1, gW1);
        cudaFuncSetAttribute(att_kernel, cudaFuncAttributeMaxDynamicSharedMemorySize,
                             SMEM_TOTAL);
    }

    prep_w_kernel<<<DIN, 256>>>(W0, pW0);
    prep_w_kernel<<<HID, 256>>>(W1, pW1);
    zero_norm_kernel<<<NG / 256, 256>>>();
    att_kernel<<<NCTA, NTHR, SMEM_TOTAL>>>(
        x, bidx, gf, b0, W2, b2,
        gamma0, beta0, mean0, var0,
        b1, gamma1, beta1, mean1, var1, out);
    norm_kernel<<<NN / 256, 256>>>(bidx, out);
}

// round 9
// speedup vs baseline: 10.7093x; 1.1123x over previous
#include <cuda_runtime.h>
#include <cuda_fp16.h>
#include <math.h>
#include <stdint.h>

#define NN   262144
#define NG   2048
#define DX   256
#define DG   128
#define DIN  384
#define HID  256
#define BN_EPS 1e-3f
#define MTILE 64
#define NCTA (NN / MTILE)
#define NTHR 256

// ---- smem byte map (71,936 B per CTA; 2 CTAs/SM) ----
// B stages: stage s @ s*16384, fragment-major 16KB per 32-k chunk
#define ABUF   32768    // A dbl-buf (GEMM1, overlays h1): buf p @ +p*9216, 64 rows x 144B
#define H1     32768    // h1 [64 m][256 k] fp16, 512B rows, XOR (r&7)<<4 ; 32KB
#define P_S0   65536
#define P_SH0  66560
#define P_S1   67584
#define P_SH1  68608
#define P_W2   69632
#define SIDX   70656    // 256B
#define PART   70912    // 1KB float[4][64]
#define SMEM_TOTAL 71936

__device__ float g_norm[NG];
// fragment-major fp16 weight images, 16KB per 32-k chunk:
// u32 index = c*4096 + ks*2048 + nw*512 + jp*128 + lane*4 + r
__device__ __align__(16) uint16_t gW0[12 * 8192];
__device__ __align__(16) uint16_t gW1[8 * 8192];

// ======================= helpers =======================
__device__ __forceinline__ uint32_t smem_u32(const void* p) {
    uint32_t a;
    asm("{ .reg .u64 t; cvta.to.shared.u64 t, %1; cvt.u32.u64 %0, t; }"
        : "=r"(a) : "l"(p));
    return a;
}
__device__ __forceinline__ void cp16(uint32_t dst, const void* src) {
    asm volatile("cp.async.cg.shared.global [%0], [%1], 16;"
                 :: "r"(dst), "l"(__cvta_generic_to_global(src)) : "memory");
}
#define CP_COMMIT() asm volatile("cp.async.commit_group;" ::: "memory")
#define CP_WAIT0()  asm volatile("cp.async.wait_group 0;" ::: "memory")
#define CP_WAIT1()  asm volatile("cp.async.wait_group 1;" ::: "memory")

__device__ __forceinline__ void mma16816h(float* c, const uint32_t* a,
                                          uint32_t b0, uint32_t b1) {
    asm volatile(
        "mma.sync.aligned.m16n8k16.row.col.f32.f16.f16.f32 "
        "{%0,%1,%2,%3}, {%4,%5,%6,%7}, {%8,%9}, {%0,%1,%2,%3};"
        : "+f"(c[0]), "+f"(c[1]), "+f"(c[2]), "+f"(c[3])
        : "r"(a[0]), "r"(a[1]), "r"(a[2]), "r"(a[3]), "r"(b0), "r"(b1));
}
__device__ __forceinline__ void ldsm4(uint32_t* d, uint32_t addr) {
    asm volatile("ldmatrix.sync.aligned.m8n8.x4.shared.b16 {%0,%1,%2,%3}, [%4];"
                 : "=r"(d[0]), "=r"(d[1]), "=r"(d[2]), "=r"(d[3]) : "r"(addr));
}
__device__ __forceinline__ uint32_t pack2h(float a, float b) {
    __half2 h = __floats2half2_rn(a, b);
    return *(uint32_t*)&h;
}

// ======================= small kernels =======================
__global__ void zero_norm_kernel() {
    g_norm[blockIdx.x * 256 + threadIdx.x] = 0.0f;
}

// W:[K,256] row-major -> fragment-major fp16 image.
// u32 idx -> (c, ks, nw, jp, lane, r): value = {W[kg][n], W[kg+1][n]}
//   j = jp*2 + (r>>1); n = nw*64 + j*8 + (lane>>2)
//   kg = c*32 + ks*16 + 2*(lane&3) + 8*(r&1)
__global__ void prep_w_kernel(const float* __restrict__ W, uint32_t* __restrict__ dst) {
    int idx = blockIdx.x * 256 + threadIdx.x;
    int c    = idx >> 12;
    int ks   = (idx >> 11) & 1;
    int nw   = (idx >> 9) & 3;
    int jp   = (idx >> 7) & 3;
    int lane = (idx >> 2) & 31;
    int r    = idx & 3;
    int j = jp * 2 + (r >> 1);
    int n = nw * 64 + j * 8 + (lane >> 2);
    int kg = c * 32 + ks * 16 + 2 * (lane & 3) + 8 * (r & 1);
    uint32_t lo = __half_as_ushort(__float2half(W[(size_t)kg * 256 + n]));
    uint32_t hi = __half_as_ushort(__float2half(W[(size_t)(kg + 1) * 256 + n]));
    dst[idx] = lo | (hi << 16);
}

__global__ void norm_kernel(const int* __restrict__ bidx, float* __restrict__ out) {
    int i = blockIdx.x * 256 + threadIdx.x;
    out[i] = out[i] / g_norm[bidx[i]];
}

// ======================= device sub-steps =======================
// cp.async one 16KB fragment-major weight chunk into stage g&1
__device__ __forceinline__ void issueB(uint32_t sb, int g, int tid) {
    const uint16_t* src = (g < 12) ? (gW0 + g * 8192) : (gW1 + (g - 12) * 8192);
    uint32_t d = sb + (uint32_t)(g & 1) * 16384u;
    #pragma unroll
    for (int i = tid; i < 1024; i += NTHR)
        cp16(d + i * 16, (const char*)src + i * 16);
}

// register-pipelined A chunk load: 64 rows x 32 k fp32 -> 2 float4 per thread
__device__ __forceinline__ void ldgA(int c, const float* x, const float* gf,
                                     const int* sidx, int row0, int tid,
                                     float4& f0, float4& f1) {
    int r = tid >> 2, q = tid & 3;
    const float* src = (c < 8)
        ? (x + (size_t)(row0 + r) * DX + c * 32 + q * 8)
        : (gf + (size_t)sidx[r] * DG + (c - 8) * 32 + q * 8);
    f0 = *(const float4*)src;
    f1 = *((const float4*)src + 1);
}

// fp16-convert 8 floats -> single STS.128 into A buf p (144B rows, no XOR)
__device__ __forceinline__ void stsA(char* smc, int p, float4 f0, float4 f1, int tid) {
    int r = tid >> 2, q = tid & 3;
    uint32_t off = ABUF + (uint32_t)p * 9216u + (uint32_t)(r * 144 + q * 16);
    *(uint4*)(smc + off) = make_uint4(pack2h(f0.x, f0.y), pack2h(f0.z, f0.w),
                                      pack2h(f1.x, f1.y), pack2h(f1.z, f1.w));
}

// ======================= main fused kernel =======================
__global__ __launch_bounds__(NTHR, 2) void att_kernel(
    const float* __restrict__ x, const int* __restrict__ bidx,
    const float* __restrict__ gf,
    const float* __restrict__ b0,
    const float* __restrict__ W2, const float* __restrict__ b2,
    const float* __restrict__ gamma0, const float* __restrict__ beta0,
    const float* __restrict__ mean0, const float* __restrict__ var0,
    const float* __restrict__ b1,
    const float* __restrict__ gamma1, const float* __restrict__ beta1,
    const float* __restrict__ mean1, const float* __restrict__ var1,
    float* __restrict__ out)
{
    extern __shared__ char smc[];
    const uint32_t sb = smem_u32(smc);
    const int tid = threadIdx.x;
    const int wid = tid >> 5;
    const int lane = tid & 31;
    const int row0 = blockIdx.x * MTILE;
    const int mw = wid >> 2;          // 0..1  M groups of 32
    const int nw = wid & 3;           // 0..3  N groups of 64
    const int qr = lane >> 2;         // 0..7
    const int l15 = lane & 15;        // ldmatrix row-within-16
    const int lk  = (lane >> 4) << 4; // ldmatrix k-half byte offset

    int* sidx = (int*)(smc + SIDX);
    if (tid < MTILE) sidx[tid] = bidx[row0 + tid];
    {   // fold BN params (256 threads = 256 cols)
        int cc = tid;
        float s0v = gamma0[cc] * rsqrtf(var0[cc] + BN_EPS);
        ((float*)(smc + P_S0))[cc]  = s0v;
        ((float*)(smc + P_SH0))[cc] = fmaf(b0[cc] - mean0[cc], s0v, beta0[cc]);
        float s1v = gamma1[cc] * rsqrtf(var1[cc] + BN_EPS);
        ((float*)(smc + P_S1))[cc]  = s1v;
        ((float*)(smc + P_SH1))[cc] = fmaf(b1[cc] - mean1[cc], s1v, beta1[cc]);
        ((float*)(smc + P_W2))[cc]  = W2[cc];
    }

    // prologue: stage W0 c0+c1, convert A(0)
    issueB(sb, 0, tid); CP_COMMIT();
    issueB(sb, 1, tid); CP_COMMIT();
    {
        float4 f0, f1;
        ldgA(0, x, gf, sidx, row0, tid, f0, f1);
        stsA(smc, 0, f0, f1, tid);
    }
    CP_WAIT1();
    __syncthreads();

    float C[2][8][4];
    #pragma unroll
    for (int i = 0; i < 2; i++)
        #pragma unroll
        for (int j = 0; j < 8; j++)
            #pragma unroll
            for (int p = 0; p < 4; p++) C[i][j][p] = 0.0f;

    const uint32_t bfrag = (uint32_t)(nw * 2048 + lane * 16);

    // =================== GEMM1: [64 x 384] @ W0 (12 x 32k chunks) ===================
    for (int i = 0; i < 12; i++) {
        float4 fA0, fA1;
        if (i + 1 < 12) ldgA(i + 1, x, gf, sidx, row0, tid, fA0, fA1);

        {   // MMA(i): stage i&1, abuf i&1
            const uint32_t bs = sb + (uint32_t)(i & 1) * 16384u;
            const uint32_t ab = sb + ABUF + (uint32_t)(i & 1) * 9216u;
            #pragma unroll
            for (int ks = 0; ks < 2; ks++) {
                uint32_t a[2][4];
                #pragma unroll
                for (int m = 0; m < 2; m++) {
                    int row = mw * 32 + m * 16 + l15;
                    ldsm4(a[m], ab + (uint32_t)(row * 144 + ks * 32) + lk);
                }
                #pragma unroll
                for (int jp = 0; jp < 4; jp++) {
                    uint4 bv = *(const uint4*)(smc + (bs - sb) + ks * 8192 + bfrag + jp * 512);
                    mma16816h(C[0][jp * 2],     a[0], bv.x, bv.y);
                    mma16816h(C[0][jp * 2 + 1], a[0], bv.z, bv.w);
                    mma16816h(C[1][jp * 2],     a[1], bv.x, bv.y);
                    mma16816h(C[1][jp * 2 + 1], a[1], bv.z, bv.w);
                }
            }
        }

        if (i + 1 < 12) stsA(smc, (i + 1) & 1, fA0, fA1, tid);
        CP_WAIT0();
        __syncthreads();
        issueB(sb, i + 2, tid);     // tail issues W1 c0/c1 (g=12,13)
        CP_COMMIT();
    }

    // ====== Epilogue 1: BN0+ReLU, fp16 convert, write h1 (overlaps W1 copies) ======
    {
        const float* sS0  = (const float*)(smc + P_S0);
        const float* sSH0 = (const float*)(smc + P_SH0);
        #pragma unroll
        for (int m = 0; m < 2; m++) {
            int r = mw * 32 + m * 16 + qr;
            uint32_t xr0 = (uint32_t)(qr << 4);
            uint32_t rb0 = (uint32_t)(r * 512);
            uint32_t rb1 = (uint32_t)((r + 8) * 512);
            #pragma unroll
            for (int j = 0; j < 8; j++) {
                int col = nw * 64 + j * 8 + (lane & 3) * 2;
                float s0a = sS0[col], s0b = sS0[col + 1];
                float h0a = sSH0[col], h0b = sSH0[col + 1];
                float v00 = fmaxf(fmaf(C[m][j][0], s0a, h0a), 0.f);
                float v01 = fmaxf(fmaf(C[m][j][1], s0b, h0b), 0.f);
                float v10 = fmaxf(fmaf(C[m][j][2], s0a, h0a), 0.f);
                float v11 = fmaxf(fmaf(C[m][j][3], s0b, h0b), 0.f);
                uint32_t ko = ((uint32_t)(col * 2)) ^ xr0;
                *(uint32_t*)(smc + H1 + rb0 + ko) = pack2h(v00, v01);
                *(uint32_t*)(smc + H1 + rb1 + ko) = pack2h(v10, v11);
            }
        }
    }
    CP_WAIT0();          // W1 c0+c1 landed
    __syncthreads();     // h1 visible

    #pragma unroll
    for (int i = 0; i < 2; i++)
        #pragma unroll
        for (int j = 0; j < 8; j++)
            #pragma unroll
            for (int p = 0; p < 4; p++) C[i][j][p] = 0.0f;

    // =================== GEMM2: h1 [64 x 256] @ W1 (8 x 32k chunks) ===================
    for (int i = 0; i < 8; i++) {
        {   // MMA(i): stage i&1 (W1 chunk i), A from h1 (ldmatrix, 16B-XOR layout)
            const uint32_t bsoff = (uint32_t)(i & 1) * 16384u;
            #pragma unroll
            for (int ks = 0; ks < 2; ks++) {
                uint32_t a[2][4];
                #pragma unroll
                for (int m = 0; m < 2; m++) {
                    int row = mw * 32 + m * 16 + l15;
                    uint32_t kb = (uint32_t)(i * 64 + ks * 32) + (uint32_t)lk;
                    ldsm4(a[m], sb + H1 + (uint32_t)(row * 512) +
                                 (kb ^ ((uint32_t)(row & 7) << 4)));
                }
                #pragma unroll
                for (int jp = 0; jp < 4; jp++) {
                    uint4 bv = *(const uint4*)(smc + bsoff + ks * 8192 + bfrag + jp * 512);
                    mma16816h(C[0][jp * 2],     a[0], bv.x, bv.y);
                    mma16816h(C[0][jp * 2 + 1], a[0], bv.z, bv.w);
                    mma16816h(C[1][jp * 2],     a[1], bv.x, bv.y);
                    mma16816h(C[1][jp * 2 + 1], a[1], bv.z, bv.w);
                }
            }
        }
        CP_WAIT0();
        __syncthreads();
        if (i + 2 < 8) { issueB(sb, 12 + i + 2, tid); CP_COMMIT(); }
    }

    // ====== Epilogue 2: BN1+ReLU, dot W2, reduce, exp, segment atomics ======
    {
        const float* sS1  = (const float*)(smc + P_S1);
        const float* sSH1 = (const float*)(smc + P_SH1);
        const float* sW2  = (const float*)(smc + P_W2);
        float pl[2][2] = {{0.f, 0.f}, {0.f, 0.f}};
        #pragma unroll
        for (int m = 0; m < 2; m++) {
            #pragma unroll
            for (int j = 0; j < 8; j++) {
                int col = nw * 64 + j * 8 + (lane & 3) * 2;
                float s1a = sS1[col], s1b = sS1[col + 1];
                float h1a = sSH1[col], h1b = sSH1[col + 1];
                float w2a = sW2[col], w2b = sW2[col + 1];
                pl[m][0] = fmaf(fmaxf(fmaf(C[m][j][0], s1a, h1a), 0.f), w2a, pl[m][0]);
                pl[m][0] = fmaf(fmaxf(fmaf(C[m][j][1], s1b, h1b), 0.f), w2b, pl[m][0]);
                pl[m][1] = fmaf(fmaxf(fmaf(C[m][j][2], s1a, h1a), 0.f), w2a, pl[m][1]);
                pl[m][1] = fmaf(fmaxf(fmaf(C[m][j][3], s1b, h1b), 0.f), w2b, pl[m][1]);
            }
        }
        #pragma unroll
        for (int off = 1; off <= 2; off <<= 1)
            #pragma unroll
            for (int m = 0; m < 2; m++) {
                pl[m][0] += __shfl_xor_sync(0xffffffffu, pl[m][0], off);
                pl[m][1] += __shfl_xor_sync(0xffffffffu, pl[m][1], off);
            }
        float* part = (float*)(smc + PART);
        if ((lane & 3) == 0) {
            #pragma unroll
            for (int m = 0; m < 2; m++) {
                int r = mw * 32 + m * 16 + qr;
                part[nw * 64 + r]     = pl[m][0];
                part[nw * 64 + r + 8] = pl[m][1];
            }
        }
        __syncthreads();
        if (tid < MTILE) {
            float logit = part[tid] + part[64 + tid] + part[128 + tid] +
                          part[192 + tid] + b2[0];
            float av = expf(logit);
            out[row0 + tid] = av;
            atomicAdd(&g_norm[sidx[tid]], av);
        }
    }
}

// ======================= launch =======================
extern "C" void kernel_launch(void* const* d_in, const int* in_sizes, int n_in,
                              void* d_out, int out_size) {
    const float* x      = (const float*)d_in[0];
    const int*   bidx   = (const int*)  d_in[1];
    const float* gf     = (const float*)d_in[2];
    const float* W0     = (const float*)d_in[3];
    const float* b0     = (const float*)d_in[4];
    const float* W1     = (const float*)d_in[5];
    const float* b1     = (const float*)d_in[6];
    const float* W2     = (const float*)d_in[7];
    const float* b2     = (const float*)d_in[8];
    const float* gamma0 = (const float*)d_in[9];
    const float* beta0  = (const float*)d_in[10];
    const float* mean0  = (const float*)d_in[11];
    const float* var0   = (const float*)d_in[12];
    const float* gamma1 = (const float*)d_in[13];
    const float* beta1  = (const float*)d_in[14];
    const float* mean1  = (const float*)d_in[15];
    const float* var1   = (const float*)d_in[16];
    float* out = (float*)d_out;

    static uint32_t *pW0 = nullptr, *pW1;
    if (!pW0) {
        cudaGetSymbolAddress((void**)&pW0, gW0);
        cudaGetSymbolAddress((void**)&pW1, gW1);
        cudaFuncSetAttribute(att_kernel, cudaFuncAttributeMaxDynamicSharedMemorySize,
                             SMEM_TOTAL);
    }

    prep_w_kernel<<<192, 256>>>(W0, pW0);   // 12 chunks * 4096 u32
    prep_w_kernel<<<128, 256>>>(W1, pW1);   // 8 chunks * 4096 u32
    zero_norm_kernel<<<NG / 256, 256>>>();
    att_kernel<<<NCTA, NTHR, SMEM_TOTAL>>>(
        x, bidx, gf, b0, W2, b2,
        gamma0, beta0, mean0, var0,
        b1, gamma1, beta1, mean1, var1, out);
    norm_kernel<<<NN / 256, 256>>>(bidx, out);
}